// round 13
// baseline (speedup 1.0000x reference)
#include <cuda_runtime.h>
#include <cuda_fp16.h>
#include <cstdint>

// Problem constants (fixed shapes from reference)
#define CB 4
#define CT 8192
#define CD 1024
#define CH 1024
#define CO 1024
#define CM (CB*CT)    // 32768 rows
#define NCHUNK 64
#define CHUNK (CT/NCHUNK)   // 128
#define LN_EPS 1e-5f

// ---------------- scratch (device globals; no allocation allowed) -------------
__device__ __half g_xh[(size_t)CM*CD];
__device__ __half g_w1h[(size_t)CH*CD], g_w2h[(size_t)CH*CD];
__device__ __half g_w3h[(size_t)CO*CH];
__device__ __half g_ihh[(size_t)CM*CH];   // raw ih (fp16)
__device__ __half g_gth[(size_t)CM*CH];   // raw gate (fp16)
__device__ __half2 g_PH[(size_t)CM*CH];   // interleaved (prefix-prod, local-h)
__device__ __half g_hnh[(size_t)CM*CH];
__device__ float g_cA[CB*NCHUNK*CH];
__device__ float g_cB[CB*NCHUNK*CH];
__device__ float g_pref[CB*NCHUNK*CH];

// ------------------------------ helpers ---------------------------------------
__device__ __forceinline__ uint32_t s2u(const void* p) {
    return (uint32_t)__cvta_generic_to_shared(p);
}
__device__ __forceinline__ void cp16(uint32_t s, const void* g) {
    asm volatile("cp.async.cg.shared.global [%0], [%1], 16;" :: "r"(s), "l"(g));
}
#define CP_COMMIT() asm volatile("cp.async.commit_group;" ::: "memory")

__device__ __forceinline__ void ldsm4(uint32_t* r, uint32_t addr) {
    asm volatile("ldmatrix.sync.aligned.m8n8.x4.shared.b16 {%0,%1,%2,%3}, [%4];"
        : "=r"(r[0]), "=r"(r[1]), "=r"(r[2]), "=r"(r[3]) : "r"(addr));
}

#define MMA_F16(d, a, b) \
    asm volatile("mma.sync.aligned.m16n8k16.row.col.f32.f16.f16.f32 " \
        "{%0,%1,%2,%3}, {%4,%5,%6,%7}, {%8,%9}, {%0,%1,%2,%3};" \
        : "+f"(d[0]), "+f"(d[1]), "+f"(d[2]), "+f"(d[3]) \
        : "r"(a[0]), "r"(a[1]), "r"(a[2]), "r"(a[3]), "r"(b[0]), "r"(b[1]))

// -------- fused fp32 -> fp16 convert, 16 elements per thread -------------------
// grid: nbx blocks for x, then nbw for each of w1,w2,w3 (16 el/thread each)
__global__ __launch_bounds__(256) void tofp16_all(
    const float* __restrict__ x,  __half* __restrict__ xh,  int nbx,
    const float* __restrict__ w1, __half* __restrict__ w1h, int nbw,
    const float* __restrict__ w2, __half* __restrict__ w2h,
    const float* __restrict__ w3, __half* __restrict__ w3h)
{
    int bx = blockIdx.x;
    const float* src;
    __half* dst;
    if (bx < nbx)            { src = x;  dst = xh;  }
    else if (bx < nbx+nbw)   { src = w1; dst = w1h; bx -= nbx; }
    else if (bx < nbx+2*nbw) { src = w2; dst = w2h; bx -= nbx + nbw; }
    else                     { src = w3; dst = w3h; bx -= nbx + 2*nbw; }
    size_t i = ((size_t)bx * 256 + threadIdx.x) * 16;
#pragma unroll
    for (int q = 0; q < 4; q++) {
        float4 v = *reinterpret_cast<const float4*>(src + i + q * 4);
        __half2* pd = reinterpret_cast<__half2*>(dst + i + q * 4);
        pd[0] = __floats2half2_rn(v.x, v.y);
        pd[1] = __floats2half2_rn(v.z, v.w);
    }
}

// ------------------ single-pass fp16 GEMM (single or dual) --------------------
// C[m][n] = sum_k A[m][k]*B[n][k] (+bias[n]).
// Dual mode (B2 != nullptr): gridDim.x = 2G, bx<G -> set1 tile bx, else set2.
// Single mode (B2 == nullptr): gridDim.x = N/128.
// 128x128 tile, BK=64, 3-stage cp.async, ldmatrix.x4, XOR swizzle, 2 CTAs/SM.

#define PART_B 16384               // 128 rows x 128B (64 halves)
#define STAGE_F16 (2*PART_B)       // A|B = 32KB per stage
#define NSTAGE 3
#define DYN_F16 (NSTAGE*STAGE_F16 + 1024)

template<typename OutT>
__global__ __launch_bounds__(256, 2) void gemm_f16(
    const __half* __restrict__ A,
    const __half* __restrict__ B1, const __half* __restrict__ B2,
    const float* __restrict__ bias1, const float* __restrict__ bias2,
    OutT* __restrict__ C1, OutT* __restrict__ C2,
    int M, int N, int K)
{
    extern __shared__ char dyn[];
    const uint32_t tile = (s2u(dyn) + 127u) & ~127u;

    const int tid = threadIdx.x;
    const int bx = blockIdx.x;

    const __half* B;
    const float* bias;
    OutT* C;
    int n0;
    if (B2 == nullptr) {                 // single-output mode
        B = B1; bias = bias1; C = C1; n0 = bx * 128;
    } else {                             // dual-output mode
        const int halfg = gridDim.x >> 1;
        const bool first = bx < halfg;
        B = first ? B1 : B2;
        bias = first ? bias1 : bias2;
        C = first ? C1 : C2;
        n0 = (first ? bx : bx - halfg) * 128;
    }
    const int m0 = blockIdx.y * 128;

    const int wid = tid >> 5, lane = tid & 31;
    const int wm = wid >> 2;
    const int wn = wid & 3;

    const __half* srcs[2] = { A + (size_t)m0 * K, B + (size_t)n0 * K };

    const int lr = tid >> 1;
    const int lc0 = (tid & 1) * 4;
    const int lsw = lr & 7;

    auto issue = [&](int s) {
        uint32_t sb = tile + (uint32_t)(s % NSTAGE) * STAGE_F16;
        int k0 = s * 64;
#pragma unroll
        for (int p = 0; p < 2; p++) {
            const __half* g = srcs[p] + (size_t)lr * K + k0 + lc0 * 8;
            uint32_t base = sb + p * PART_B + lr * 128;
#pragma unroll
            for (int c = 0; c < 4; c++)
                cp16(base + (((lc0 + c) ^ lsw) << 4), g + c * 8);
        }
        CP_COMMIT();
    };

    const int arow = wm * 64 + (lane & 15);
    const int ahalf = lane >> 4;
    const int asw = arow & 7;
    const int brow = wn * 32 + ((lane >> 4) << 3) + (lane & 7);
    const int bhalf = (lane >> 3) & 1;
    const int bsw = brow & 7;

    float acc[4][4][4];
#pragma unroll
    for (int i = 0; i < 4; i++)
#pragma unroll
        for (int j = 0; j < 4; j++)
#pragma unroll
            for (int c = 0; c < 4; c++) acc[i][j][c] = 0.f;

    issue(0); issue(1);

    const int NIT = K / 64;
    for (int it = 0; it < NIT; ++it) {
        if (it + 1 < NIT) asm volatile("cp.async.wait_group 1;" ::: "memory");
        else              asm volatile("cp.async.wait_group 0;" ::: "memory");
        __syncthreads();
        if (it + 2 < NIT) issue(it + 2);

        uint32_t sb = tile + (uint32_t)(it % NSTAGE) * STAGE_F16;
        uint32_t aA = sb          + arow * 128;
        uint32_t aB = sb + PART_B + brow * 128;

#pragma unroll
        for (int ks = 0; ks < 4; ks++) {
            const int ac = (2 * ks + ahalf) ^ asw;
            const int bc = (2 * ks + bhalf) ^ bsw;
            uint32_t a[4][4], b[4][2];
#pragma unroll
            for (int i = 0; i < 4; i++)
                ldsm4(a[i], aA + i * (16 * 128) + (ac << 4));
#pragma unroll
            for (int q = 0; q < 2; q++) {
                uint32_t rb[4];
                ldsm4(rb, aB + q * (16 * 128) + (bc << 4));
                b[q*2+0][0] = rb[0]; b[q*2+0][1] = rb[1];
                b[q*2+1][0] = rb[2]; b[q*2+1][1] = rb[3];
            }
#pragma unroll
            for (int i = 0; i < 4; i++)
#pragma unroll
                for (int j = 0; j < 4; j++)
                    MMA_F16(acc[i][j], a[i], b[j]);
        }
    }

    const int g = lane >> 2, tq = lane & 3;
#pragma unroll
    for (int i = 0; i < 4; i++) {
        const int m = m0 + wm * 64 + i * 16 + g;
#pragma unroll
        for (int j = 0; j < 4; j++) {
            const int n = n0 + wn * 32 + j * 8 + tq * 2;
            float b0 = 0.f, b1 = 0.f;
            if (bias) { b0 = bias[n]; b1 = bias[n + 1]; }
            float o00 = acc[i][j][0] + b0, o01 = acc[i][j][1] + b1;
            float o10 = acc[i][j][2] + b0, o11 = acc[i][j][3] + b1;
            if constexpr (sizeof(OutT) == 2) {
                __half2* p0 = reinterpret_cast<__half2*>((__half*)C + (size_t)m * N + n);
                __half2* p1 = reinterpret_cast<__half2*>((__half*)C + (size_t)(m + 8) * N + n);
                *p0 = __floats2half2_rn(o00, o01);
                *p1 = __floats2half2_rn(o10, o11);
            } else {
                float2 v0 = { o00, o01 }, v1 = { o10, o11 };
                *reinterpret_cast<float2*>((float*)C + (size_t)m * N + n)       = v0;
                *reinterpret_cast<float2*>((float*)C + (size_t)(m + 8) * N + n) = v1;
            }
        }
    }
}

// ---- pass A (fused, scalar): elementwise + local scan; interleaved PH out ----
__global__ __launch_bounds__(256) void scan_local(
    const __half* __restrict__ ih_raw, const __half* __restrict__ gt_raw,
    __half2* __restrict__ PH,
    const float* __restrict__ b_ih, const float* __restrict__ b_g,
    const float* __restrict__ log_a,
    float* __restrict__ cA, float* __restrict__ cB)
{
    int idx = blockIdx.x * blockDim.x + threadIdx.x;
    int h = idx % CH;
    int c = (idx / CH) % NCHUNK;
    int b = idx / (CH * NCHUNK);
    const float bg = b_g[h], bi = b_ih[h], ea = __expf(log_a[h]);
    size_t base = ((size_t)b * CT + (size_t)c * CHUNK) * CH + h;
    float p = 1.f, hl = 0.f;
#pragma unroll 8
    for (int t = 0; t < CHUNK; t++) {
        size_t o = base + (size_t)t * CH;
        float graw = __half2float(gt_raw[o]);
        float iraw = __half2float(ih_raw[o]);
        float gate = 1.f / (1.f + __expf(-(graw + bg)));
        float beta = gate * (iraw + bi);
        float a = (1.f - gate) * ea;
        hl = fmaf(a, hl, beta);
        p *= a;
        PH[o] = __halves2half2(__float2half_rn(p), __float2half_rn(hl));
    }
    cA[((size_t)b * NCHUNK + c) * CH + h] = p;
    cB[((size_t)b * NCHUNK + c) * CH + h] = hl;
}

// ---------------- pass B: scan across chunk summaries per (b,h) ---------------
__global__ __launch_bounds__(256) void scan_carry(
    const float* __restrict__ cA, const float* __restrict__ cB,
    float* __restrict__ pref)
{
    int idx = blockIdx.x * blockDim.x + threadIdx.x;
    int h = idx % CH;
    int b = idx / CH;
    float run = 0.f;
#pragma unroll
    for (int c = 0; c < NCHUNK; c++) {
        size_t o = ((size_t)b * NCHUNK + c) * CH + h;
        pref[o] = run;
        run = fmaf(cA[o], run, cB[o]);
    }
}

// ------- pass C: fixup h = h_local + P*carry, fused LayerNorm -> fp16 ----------
__global__ __launch_bounds__(256) void fix_ln(
    const __half2* __restrict__ PH,
    const float* __restrict__ pref,
    const float* __restrict__ lng, const float* __restrict__ lnb,
    __half* __restrict__ hnh)
{
    __shared__ float sred[16];
    const int row = blockIdx.x;
    const int b = row / CT;
    const int t = row % CT;
    const int c = t / CHUNK;
    const size_t base = (size_t)row * CH;
    const float* prow = pref + ((size_t)b * NCHUNK + c) * CH;
    const int h = threadIdx.x * 4;

    uint4 q = *reinterpret_cast<const uint4*>(PH + base + h);  // 4 (p,hl) pairs
    float2 q0 = __half22float2(*reinterpret_cast<__half2*>(&q.x));
    float2 q1 = __half22float2(*reinterpret_cast<__half2*>(&q.y));
    float2 q2 = __half22float2(*reinterpret_cast<__half2*>(&q.z));
    float2 q3 = __half22float2(*reinterpret_cast<__half2*>(&q.w));
    float4 pr4 = *reinterpret_cast<const float4*>(prow + h);
    float v[4];
    v[0] = fmaf(q0.x, pr4.x, q0.y);
    v[1] = fmaf(q1.x, pr4.y, q1.y);
    v[2] = fmaf(q2.x, pr4.z, q2.y);
    v[3] = fmaf(q3.x, pr4.w, q3.y);

    float s = v[0] + v[1] + v[2] + v[3];
    float ss = v[0]*v[0] + v[1]*v[1] + v[2]*v[2] + v[3]*v[3];
#pragma unroll
    for (int off = 16; off > 0; off >>= 1) {
        s  += __shfl_xor_sync(0xffffffffu, s,  off);
        ss += __shfl_xor_sync(0xffffffffu, ss, off);
    }
    const int warp = threadIdx.x >> 5, lane = threadIdx.x & 31;
    if (lane == 0) { sred[warp] = s; sred[8 + warp] = ss; }
    __syncthreads();
    if (threadIdx.x < 32) {
        float a  = (lane < 8) ? sred[lane]     : 0.f;
        float b2 = (lane < 8) ? sred[8 + lane] : 0.f;
#pragma unroll
        for (int off = 4; off > 0; off >>= 1) {
            a  += __shfl_xor_sync(0xffffffffu, a,  off);
            b2 += __shfl_xor_sync(0xffffffffu, b2, off);
        }
        if (lane == 0) { sred[0] = a; sred[1] = b2; }
    }
    __syncthreads();
    const float mu  = sred[0] * (1.f / CH);
    const float var = sred[1] * (1.f / CH) - mu * mu;
    const float inv = rsqrtf(var + LN_EPS);

    float4 g4 = *reinterpret_cast<const float4*>(lng + h);
    float4 b4 = *reinterpret_cast<const float4*>(lnb + h);
    float o[4];
    o[0] = (v[0] - mu) * inv * g4.x + b4.x;
    o[1] = (v[1] - mu) * inv * g4.y + b4.y;
    o[2] = (v[2] - mu) * inv * g4.z + b4.z;
    o[3] = (v[3] - mu) * inv * g4.w + b4.w;

    uint2 ou;
    *reinterpret_cast<__half2*>(&ou.x) = __floats2half2_rn(o[0], o[1]);
    *reinterpret_cast<__half2*>(&ou.y) = __floats2half2_rn(o[2], o[3]);
    *reinterpret_cast<uint2*>(hnh + base + h) = ou;
}

// --------------------------------- launcher ----------------------------------
extern "C" void kernel_launch(void* const* d_in, const int* in_sizes, int n_in,
                              void* d_out, int out_size)
{
    const float* x      = (const float*)d_in[0];
    const float* W_ih   = (const float*)d_in[1];
    const float* b_ih   = (const float*)d_in[2];
    const float* log_a  = (const float*)d_in[3];
    const float* W_gate = (const float*)d_in[4];
    const float* b_gate = (const float*)d_in[5];
    const float* W_out  = (const float*)d_in[6];
    const float* b_out  = (const float*)d_in[7];
    const float* ln_g   = (const float*)d_in[8];
    const float* ln_b   = (const float*)d_in[9];
    float* out = (float*)d_out;

    __half *xh, *w1h, *w2h, *w3h, *ihh, *gth, *hnh;
    __half2 *PH;
    float *cA, *cB, *pref;
    cudaGetSymbolAddress((void**)&xh,   g_xh);
    cudaGetSymbolAddress((void**)&w1h,  g_w1h);
    cudaGetSymbolAddress((void**)&w2h,  g_w2h);
    cudaGetSymbolAddress((void**)&w3h,  g_w3h);
    cudaGetSymbolAddress((void**)&ihh,  g_ihh);
    cudaGetSymbolAddress((void**)&gth,  g_gth);
    cudaGetSymbolAddress((void**)&hnh,  g_hnh);
    cudaGetSymbolAddress((void**)&PH,   g_PH);
    cudaGetSymbolAddress((void**)&cA,   g_cA);
    cudaGetSymbolAddress((void**)&cB,   g_cB);
    cudaGetSymbolAddress((void**)&pref, g_pref);

    cudaFuncSetAttribute(gemm_f16<__half>,
                         cudaFuncAttributeMaxDynamicSharedMemorySize, DYN_F16);
    cudaFuncSetAttribute(gemm_f16<float>,
                         cudaFuncAttributeMaxDynamicSharedMemorySize, DYN_F16);

    // fused conversions (16 el/thread): x (8192 blocks) + w1/w2/w3 (256 each)
    const int NBX = (int)((size_t)CM * CD / 16 / 256);  // 8192
    const int NBW = (int)((size_t)CH * CD / 16 / 256);  // 256
    tofp16_all<<<NBX + 3 * NBW, 256>>>(
        x, xh, NBX, W_ih, w1h, NBW, W_gate, w2h, W_out, w3h);

    // fused dual input GEMM (fp16 -> fp16 out): bx<8 -> ih, bx>=8 -> gate
    gemm_f16<__half><<<dim3(16, CM / 128), 256, DYN_F16>>>(
        xh, w1h, w2h, nullptr, nullptr, ihh, gth, CM, CH, CD);

    // fused elementwise + chunked scan (scalar, high occupancy)
    scan_local<<<(CB * CH * NCHUNK) / 256, 256>>>(
        ihh, gth, PH, b_ih, b_gate, log_a, cA, cB);
    scan_carry<<<(CB * CH) / 256, 256>>>(cA, cB, pref);
    fix_ln<<<CM, 256>>>(PH, pref, ln_g, ln_b, hnh);

    // output GEMM: single-output mode, grid.x = CO/128 = 8
    gemm_f16<float><<<dim3(CO / 128, CM / 128), 256, DYN_F16>>>(
        hnh, w3h, nullptr, b_out, nullptr, out, nullptr, CM, CO, CH);
}

// round 14
// speedup vs baseline: 1.0422x; 1.0422x over previous
#include <cuda_runtime.h>
#include <cuda_fp16.h>
#include <cstdint>

// Problem constants (fixed shapes from reference)
#define CB 4
#define CT 8192
#define CD 1024
#define CH 1024
#define CO 1024
#define CM (CB*CT)    // 32768 rows
#define NCHUNK 128
#define CHUNK (CT/NCHUNK)   // 64
#define LN_EPS 1e-5f

// ---------------- scratch (device globals; no allocation allowed) -------------
__device__ __half g_xh[(size_t)CM*CD];
__device__ __half g_w1h[(size_t)CH*CD], g_w2h[(size_t)CH*CD];
__device__ __half g_w3h[(size_t)CO*CH];
__device__ __half2 g_PH[(size_t)CM*CH];   // interleaved (prefix-prod, local-h)
__device__ __half g_hnh[(size_t)CM*CH];
__device__ float g_cA[CB*NCHUNK*CH];
__device__ float g_cB[CB*NCHUNK*CH];
__device__ float g_pref[CB*NCHUNK*CH];

// ------------------------------ helpers ---------------------------------------
__device__ __forceinline__ uint32_t s2u(const void* p) {
    return (uint32_t)__cvta_generic_to_shared(p);
}
__device__ __forceinline__ void cp16(uint32_t s, const void* g) {
    asm volatile("cp.async.cg.shared.global [%0], [%1], 16;" :: "r"(s), "l"(g));
}
#define CP_COMMIT() asm volatile("cp.async.commit_group;" ::: "memory")

__device__ __forceinline__ void ldsm4(uint32_t* r, uint32_t addr) {
    asm volatile("ldmatrix.sync.aligned.m8n8.x4.shared.b16 {%0,%1,%2,%3}, [%4];"
        : "=r"(r[0]), "=r"(r[1]), "=r"(r[2]), "=r"(r[3]) : "r"(addr));
}

#define MMA_F16(d, a, b) \
    asm volatile("mma.sync.aligned.m16n8k16.row.col.f32.f16.f16.f32 " \
        "{%0,%1,%2,%3}, {%4,%5,%6,%7}, {%8,%9}, {%0,%1,%2,%3};" \
        : "+f"(d[0]), "+f"(d[1]), "+f"(d[2]), "+f"(d[3]) \
        : "r"(a[0]), "r"(a[1]), "r"(a[2]), "r"(a[3]), "r"(b[0]), "r"(b[1]))

// ------------ fused fp32 -> fp16 convert for all 4 source arrays ---------------
__global__ __launch_bounds__(256) void tofp16_all(
    const float* __restrict__ x,  __half* __restrict__ xh,  int nbx,
    const float* __restrict__ w1, __half* __restrict__ w1h, int nbw,
    const float* __restrict__ w2, __half* __restrict__ w2h,
    const float* __restrict__ w3, __half* __restrict__ w3h)
{
    int bx = blockIdx.x;
    const float* src;
    __half* dst;
    if (bx < nbx)            { src = x;  dst = xh;  }
    else if (bx < nbx+nbw)   { src = w1; dst = w1h; bx -= nbx; }
    else if (bx < nbx+2*nbw) { src = w2; dst = w2h; bx -= nbx + nbw; }
    else                     { src = w3; dst = w3h; bx -= nbx + 2*nbw; }
    size_t i = ((size_t)bx * 256 + threadIdx.x) * 4;
    float4 v = *reinterpret_cast<const float4*>(src + i);
    __half2* pd = reinterpret_cast<__half2*>(dst + i);
    pd[0] = __floats2half2_rn(v.x, v.y);
    pd[1] = __floats2half2_rn(v.z, v.w);
}

// -------- FUSED: dual input GEMM (ih + gate) + elementwise + local scan -------
// Each CTA: m-tile = 128 consecutive timesteps of one batch (batch-aligned),
// n-tile = 128 h's. Computes ih AND gate (two acc sets), rounds to fp16 into a
// smem (ih,gate) half2 tile (same rounding as old global round-trip), then 256
// threads scan two 64-step half-chunks per h column -> PH + cA/cB.

#define PART_B 16384               // 128 rows x 128B (64 halves)
#define STAGE3_B (3*PART_B)        // A|W1|W2 = 48KB per stage
#define DYN3 (3*STAGE3_B + 1024)   // 148480
#define SRS 129                    // scan tile row stride in half2 words

__global__ __launch_bounds__(256, 1) void gemm_scan(
    const __half* __restrict__ A,
    const __half* __restrict__ W1, const __half* __restrict__ W2,
    const float* __restrict__ b_ih, const float* __restrict__ b_g,
    const float* __restrict__ log_a,
    __half2* __restrict__ PH, float* __restrict__ cA, float* __restrict__ cB)
{
    const int K = CD;
    extern __shared__ char dyn[];
    const uint32_t tile = (s2u(dyn) + 127u) & ~127u;
    char* gtile = dyn + (int)(tile - s2u(dyn));

    const int tid = threadIdx.x;
    const int n0 = blockIdx.x * 128;
    const int m0 = blockIdx.y * 128;

    const int wid = tid >> 5, lane = tid & 31;
    const int wm = wid >> 2;
    const int wn = wid & 3;

    const __half* srcs[3] = {
        A + (size_t)m0 * K, W1 + (size_t)n0 * K, W2 + (size_t)n0 * K };

    const int lr = tid >> 1;
    const int lc0 = (tid & 1) * 4;
    const int lsw = lr & 7;

    auto issue = [&](int s) {
        uint32_t sb = tile + (uint32_t)(s % 3) * STAGE3_B;
        int k0 = s * 64;
#pragma unroll
        for (int p = 0; p < 3; p++) {
            const __half* g = srcs[p] + (size_t)lr * K + k0 + lc0 * 8;
            uint32_t base = sb + p * PART_B + lr * 128;
#pragma unroll
            for (int c = 0; c < 4; c++)
                cp16(base + (((lc0 + c) ^ lsw) << 4), g + c * 8);
        }
        CP_COMMIT();
    };

    const int arow = wm * 64 + (lane & 15);
    const int ahalf = lane >> 4;
    const int asw = arow & 7;
    const int brow = wn * 32 + ((lane >> 4) << 3) + (lane & 7);
    const int bhalf = (lane >> 3) & 1;
    const int bsw = brow & 7;

    float acc1[4][4][4], acc2[4][4][4];
#pragma unroll
    for (int i = 0; i < 4; i++)
#pragma unroll
        for (int j = 0; j < 4; j++)
#pragma unroll
            for (int c = 0; c < 4; c++) { acc1[i][j][c] = 0.f; acc2[i][j][c] = 0.f; }

    issue(0); issue(1);

    const int NIT = K / 64;   // 16
    for (int it = 0; it < NIT; ++it) {
        if (it + 1 < NIT) asm volatile("cp.async.wait_group 1;" ::: "memory");
        else              asm volatile("cp.async.wait_group 0;" ::: "memory");
        __syncthreads();
        if (it + 2 < NIT) issue(it + 2);

        uint32_t sb = tile + (uint32_t)(it % 3) * STAGE3_B;
        uint32_t aA  = sb              + arow * 128;
        uint32_t aB1 = sb +     PART_B + brow * 128;
        uint32_t aB2 = sb + 2 * PART_B + brow * 128;

#pragma unroll
        for (int ks = 0; ks < 4; ks++) {
            const int ac = (2 * ks + ahalf) ^ asw;
            const int bc = (2 * ks + bhalf) ^ bsw;
            uint32_t a[4][4], b1[4][2], b2[4][2];
#pragma unroll
            for (int i = 0; i < 4; i++)
                ldsm4(a[i], aA + i * (16 * 128) + (ac << 4));
#pragma unroll
            for (int q = 0; q < 2; q++) {
                uint32_t rb[4];
                ldsm4(rb, aB1 + q * (16 * 128) + (bc << 4));
                b1[q*2+0][0] = rb[0]; b1[q*2+0][1] = rb[1];
                b1[q*2+1][0] = rb[2]; b1[q*2+1][1] = rb[3];
                ldsm4(rb, aB2 + q * (16 * 128) + (bc << 4));
                b2[q*2+0][0] = rb[0]; b2[q*2+0][1] = rb[1];
                b2[q*2+1][0] = rb[2]; b2[q*2+1][1] = rb[3];
            }
#pragma unroll
            for (int i = 0; i < 4; i++)
#pragma unroll
                for (int j = 0; j < 4; j++) {
                    MMA_F16(acc1[i][j], a[i], b1[j]);
                    MMA_F16(acc2[i][j], a[i], b2[j]);
                }
        }
    }
    __syncthreads();   // all smem reads done; reuse pipeline smem for scan tile

    // ---- write (ih, gate) fp16 pairs to smem scan tile: [t 0..127][h 0..127] --
    __half2* S = reinterpret_cast<__half2*>(gtile);
    const int g = lane >> 2, tq = lane & 3;
#pragma unroll
    for (int i = 0; i < 4; i++) {
        const int r0 = wm * 64 + i * 16 + g;
#pragma unroll
        for (int j = 0; j < 4; j++) {
            const int n = wn * 32 + j * 8 + tq * 2;
            S[r0 * SRS + n]           = __floats2half2_rn(acc1[i][j][0], acc2[i][j][0]);
            S[r0 * SRS + n + 1]       = __floats2half2_rn(acc1[i][j][1], acc2[i][j][1]);
            S[(r0 + 8) * SRS + n]     = __floats2half2_rn(acc1[i][j][2], acc2[i][j][2]);
            S[(r0 + 8) * SRS + n + 1] = __floats2half2_rn(acc1[i][j][3], acc2[i][j][3]);
        }
    }
    __syncthreads();

    // ---- scan: 256 threads = 128 h x 2 half-chunks of 64 timesteps ------------
    const int h = tid & 127;
    const int hs = tid >> 7;            // half-chunk 0/1
    const int hg = n0 + h;              // global h
    const float bg = b_g[hg], bi = b_ih[hg], ea = __expf(log_a[hg]);

    float p = 1.f, hl = 0.f;
    size_t grow = ((size_t)(m0 + hs * 64)) * CH + hg;
#pragma unroll 8
    for (int t = 0; t < 64; t++) {
        float2 f = __half22float2(S[(hs * 64 + t) * SRS + h]);
        float gate = 1.f / (1.f + __expf(-(f.y + bg)));
        float beta = gate * (f.x + bi);
        float a = (1.f - gate) * ea;
        hl = fmaf(a, hl, beta);
        p *= a;
        PH[grow + (size_t)t * CH] = __halves2half2(__float2half_rn(p), __float2half_rn(hl));
    }
    const int b = m0 >> 13;             // /CT
    const int c0 = (m0 & (CT - 1)) >> 6;  // /CHUNK
    size_t co = ((size_t)b * NCHUNK + c0 + hs) * CH + hg;
    cA[co] = p;
    cB[co] = hl;
}

// ------------------ single-pass fp16 GEMM (output, single mode) ---------------
#define STAGE_F16 (2*PART_B)       // A|B = 32KB per stage
#define NSTAGE 3
#define DYN_F16 (NSTAGE*STAGE_F16 + 1024)

__global__ __launch_bounds__(256, 2) void gemm_f16(
    const __half* __restrict__ A, const __half* __restrict__ B,
    const float* __restrict__ bias, float* __restrict__ C,
    int M, int N, int K)
{
    extern __shared__ char dyn[];
    const uint32_t tile = (s2u(dyn) + 127u) & ~127u;

    const int tid = threadIdx.x;
    const int n0 = blockIdx.x * 128;
    const int m0 = blockIdx.y * 128;

    const int wid = tid >> 5, lane = tid & 31;
    const int wm = wid >> 2;
    const int wn = wid & 3;

    const __half* srcs[2] = { A + (size_t)m0 * K, B + (size_t)n0 * K };

    const int lr = tid >> 1;
    const int lc0 = (tid & 1) * 4;
    const int lsw = lr & 7;

    auto issue = [&](int s) {
        uint32_t sb = tile + (uint32_t)(s % NSTAGE) * STAGE_F16;
        int k0 = s * 64;
#pragma unroll
        for (int p = 0; p < 2; p++) {
            const __half* g = srcs[p] + (size_t)lr * K + k0 + lc0 * 8;
            uint32_t base = sb + p * PART_B + lr * 128;
#pragma unroll
            for (int c = 0; c < 4; c++)
                cp16(base + (((lc0 + c) ^ lsw) << 4), g + c * 8);
        }
        CP_COMMIT();
    };

    const int arow = wm * 64 + (lane & 15);
    const int ahalf = lane >> 4;
    const int asw = arow & 7;
    const int brow = wn * 32 + ((lane >> 4) << 3) + (lane & 7);
    const int bhalf = (lane >> 3) & 1;
    const int bsw = brow & 7;

    float acc[4][4][4];
#pragma unroll
    for (int i = 0; i < 4; i++)
#pragma unroll
        for (int j = 0; j < 4; j++)
#pragma unroll
            for (int c = 0; c < 4; c++) acc[i][j][c] = 0.f;

    issue(0); issue(1);

    const int NIT = K / 64;
    for (int it = 0; it < NIT; ++it) {
        if (it + 1 < NIT) asm volatile("cp.async.wait_group 1;" ::: "memory");
        else              asm volatile("cp.async.wait_group 0;" ::: "memory");
        __syncthreads();
        if (it + 2 < NIT) issue(it + 2);

        uint32_t sb = tile + (uint32_t)(it % NSTAGE) * STAGE_F16;
        uint32_t aA = sb          + arow * 128;
        uint32_t aB = sb + PART_B + brow * 128;

#pragma unroll
        for (int ks = 0; ks < 4; ks++) {
            const int ac = (2 * ks + ahalf) ^ asw;
            const int bc = (2 * ks + bhalf) ^ bsw;
            uint32_t a[4][4], b[4][2];
#pragma unroll
            for (int i = 0; i < 4; i++)
                ldsm4(a[i], aA + i * (16 * 128) + (ac << 4));
#pragma unroll
            for (int q = 0; q < 2; q++) {
                uint32_t rb[4];
                ldsm4(rb, aB + q * (16 * 128) + (bc << 4));
                b[q*2+0][0] = rb[0]; b[q*2+0][1] = rb[1];
                b[q*2+1][0] = rb[2]; b[q*2+1][1] = rb[3];
            }
#pragma unroll
            for (int i = 0; i < 4; i++)
#pragma unroll
                for (int j = 0; j < 4; j++)
                    MMA_F16(acc[i][j], a[i], b[j]);
        }
    }

    const int g = lane >> 2, tq = lane & 3;
#pragma unroll
    for (int i = 0; i < 4; i++) {
        const int m = m0 + wm * 64 + i * 16 + g;
#pragma unroll
        for (int j = 0; j < 4; j++) {
            const int n = n0 + wn * 32 + j * 8 + tq * 2;
            float b0 = bias[n], b1 = bias[n + 1];
            float2 v0 = { acc[i][j][0] + b0, acc[i][j][1] + b1 };
            float2 v1 = { acc[i][j][2] + b0, acc[i][j][3] + b1 };
            *reinterpret_cast<float2*>(C + (size_t)m * N + n)       = v0;
            *reinterpret_cast<float2*>(C + (size_t)(m + 8) * N + n) = v1;
        }
    }
}

// ---------------- pass B: scan across chunk summaries per (b,h) ---------------
__global__ __launch_bounds__(256) void scan_carry(
    const float* __restrict__ cA, const float* __restrict__ cB,
    float* __restrict__ pref)
{
    int idx = blockIdx.x * blockDim.x + threadIdx.x;
    int h = idx % CH;
    int b = idx / CH;
    float run = 0.f;
#pragma unroll
    for (int c = 0; c < NCHUNK; c++) {
        size_t o = ((size_t)b * NCHUNK + c) * CH + h;
        pref[o] = run;
        run = fmaf(cA[o], run, cB[o]);
    }
}

// ------- pass C: fixup h = h_local + P*carry, fused LayerNorm -> fp16 ----------
__global__ __launch_bounds__(256) void fix_ln(
    const __half2* __restrict__ PH,
    const float* __restrict__ pref,
    const float* __restrict__ lng, const float* __restrict__ lnb,
    __half* __restrict__ hnh)
{
    __shared__ float sred[16];
    const int row = blockIdx.x;
    const int b = row / CT;
    const int t = row % CT;
    const int c = t / CHUNK;
    const size_t base = (size_t)row * CH;
    const float* prow = pref + ((size_t)b * NCHUNK + c) * CH;
    const int h = threadIdx.x * 4;

    uint4 q = *reinterpret_cast<const uint4*>(PH + base + h);
    float2 q0 = __half22float2(*reinterpret_cast<__half2*>(&q.x));
    float2 q1 = __half22float2(*reinterpret_cast<__half2*>(&q.y));
    float2 q2 = __half22float2(*reinterpret_cast<__half2*>(&q.z));
    float2 q3 = __half22float2(*reinterpret_cast<__half2*>(&q.w));
    float4 pr4 = *reinterpret_cast<const float4*>(prow + h);
    float v[4];
    v[0] = fmaf(q0.x, pr4.x, q0.y);
    v[1] = fmaf(q1.x, pr4.y, q1.y);
    v[2] = fmaf(q2.x, pr4.z, q2.y);
    v[3] = fmaf(q3.x, pr4.w, q3.y);

    float s = v[0] + v[1] + v[2] + v[3];
    float ss = v[0]*v[0] + v[1]*v[1] + v[2]*v[2] + v[3]*v[3];
#pragma unroll
    for (int off = 16; off > 0; off >>= 1) {
        s  += __shfl_xor_sync(0xffffffffu, s,  off);
        ss += __shfl_xor_sync(0xffffffffu, ss, off);
    }
    const int warp = threadIdx.x >> 5, lane = threadIdx.x & 31;
    if (lane == 0) { sred[warp] = s; sred[8 + warp] = ss; }
    __syncthreads();
    if (threadIdx.x < 32) {
        float a  = (lane < 8) ? sred[lane]     : 0.f;
        float b2 = (lane < 8) ? sred[8 + lane] : 0.f;
#pragma unroll
        for (int off = 4; off > 0; off >>= 1) {
            a  += __shfl_xor_sync(0xffffffffu, a,  off);
            b2 += __shfl_xor_sync(0xffffffffu, b2, off);
        }
        if (lane == 0) { sred[0] = a; sred[1] = b2; }
    }
    __syncthreads();
    const float mu  = sred[0] * (1.f / CH);
    const float var = sred[1] * (1.f / CH) - mu * mu;
    const float inv = rsqrtf(var + LN_EPS);

    float4 g4 = *reinterpret_cast<const float4*>(lng + h);
    float4 b4 = *reinterpret_cast<const float4*>(lnb + h);
    float o[4];
    o[0] = (v[0] - mu) * inv * g4.x + b4.x;
    o[1] = (v[1] - mu) * inv * g4.y + b4.y;
    o[2] = (v[2] - mu) * inv * g4.z + b4.z;
    o[3] = (v[3] - mu) * inv * g4.w + b4.w;

    uint2 ou;
    *reinterpret_cast<__half2*>(&ou.x) = __floats2half2_rn(o[0], o[1]);
    *reinterpret_cast<__half2*>(&ou.y) = __floats2half2_rn(o[2], o[3]);
    *reinterpret_cast<uint2*>(hnh + base + h) = ou;
}

// --------------------------------- launcher ----------------------------------
extern "C" void kernel_launch(void* const* d_in, const int* in_sizes, int n_in,
                              void* d_out, int out_size)
{
    const float* x      = (const float*)d_in[0];
    const float* W_ih   = (const float*)d_in[1];
    const float* b_ih   = (const float*)d_in[2];
    const float* log_a  = (const float*)d_in[3];
    const float* W_gate = (const float*)d_in[4];
    const float* b_gate = (const float*)d_in[5];
    const float* W_out  = (const float*)d_in[6];
    const float* b_out  = (const float*)d_in[7];
    const float* ln_g   = (const float*)d_in[8];
    const float* ln_b   = (const float*)d_in[9];
    float* out = (float*)d_out;

    __half *xh, *w1h, *w2h, *w3h, *hnh;
    __half2 *PH;
    float *cA, *cB, *pref;
    cudaGetSymbolAddress((void**)&xh,   g_xh);
    cudaGetSymbolAddress((void**)&w1h,  g_w1h);
    cudaGetSymbolAddress((void**)&w2h,  g_w2h);
    cudaGetSymbolAddress((void**)&w3h,  g_w3h);
    cudaGetSymbolAddress((void**)&hnh,  g_hnh);
    cudaGetSymbolAddress((void**)&PH,   g_PH);
    cudaGetSymbolAddress((void**)&cA,   g_cA);
    cudaGetSymbolAddress((void**)&cB,   g_cB);
    cudaGetSymbolAddress((void**)&pref, g_pref);

    cudaFuncSetAttribute(gemm_scan,
                         cudaFuncAttributeMaxDynamicSharedMemorySize, DYN3);
    cudaFuncSetAttribute(gemm_f16,
                         cudaFuncAttributeMaxDynamicSharedMemorySize, DYN_F16);

    // fused conversions (4 el/thread, high parallelism)
    const int NBX = (int)((size_t)CM * CD / 4 / 256);
    const int NBW = (int)((size_t)CH * CD / 4 / 256);
    tofp16_all<<<NBX + 3 * NBW, 256>>>(
        x, xh, NBX, W_ih, w1h, NBW, W_gate, w2h, W_out, w3h);

    // fused dual GEMM + elementwise + local scan
    gemm_scan<<<dim3(CH / 128, CM / 128), 256, DYN3>>>(
        xh, w1h, w2h, b_ih, b_gate, log_a, PH, cA, cB);

    scan_carry<<<(CB * CH) / 256, 256>>>(cA, cB, pref);
    fix_ln<<<CM, 256>>>(PH, pref, ln_g, ln_b, hnh);

    // output GEMM
    gemm_f16<<<dim3(CO / 128, CM / 128), 256, DYN_F16>>>(
        hnh, w3h, b_out, out, CM, CO, CH);
}

// round 15
// speedup vs baseline: 1.1466x; 1.1002x over previous
#include <cuda_runtime.h>
#include <cuda_fp16.h>
#include <cstdint>

// Problem constants (fixed shapes from reference)
#define CB 4
#define CT 8192
#define CD 1024
#define CH 1024
#define CO 1024
#define CM (CB*CT)    // 32768 rows
#define NCHUNK 128
#define CHUNK (CT/NCHUNK)   // 64
#define LN_EPS 1e-5f

// ---------------- scratch (device globals; no allocation allowed) -------------
__device__ __half g_xh[(size_t)CM*CD];
__device__ __half g_w1h[(size_t)CH*CD], g_w2h[(size_t)CH*CD];
__device__ __half g_w3h[(size_t)CO*CH];
__device__ __half2 g_PH[(size_t)CM*CH];   // interleaved (prefix-prod, local-h)
__device__ __half g_hnh[(size_t)CM*CH];
__device__ float g_cA[CB*NCHUNK*CH];
__device__ float g_cB[CB*NCHUNK*CH];
__device__ float g_pref[CB*NCHUNK*CH];

// ------------------------------ helpers ---------------------------------------
__device__ __forceinline__ uint32_t s2u(const void* p) {
    return (uint32_t)__cvta_generic_to_shared(p);
}
__device__ __forceinline__ void cp16(uint32_t s, const void* g) {
    asm volatile("cp.async.cg.shared.global [%0], [%1], 16;" :: "r"(s), "l"(g));
}
#define CP_COMMIT() asm volatile("cp.async.commit_group;" ::: "memory")

__device__ __forceinline__ void ldsm4(uint32_t* r, uint32_t addr) {
    asm volatile("ldmatrix.sync.aligned.m8n8.x4.shared.b16 {%0,%1,%2,%3}, [%4];"
        : "=r"(r[0]), "=r"(r[1]), "=r"(r[2]), "=r"(r[3]) : "r"(addr));
}

#define MMA_F16(d, a, b) \
    asm volatile("mma.sync.aligned.m16n8k16.row.col.f32.f16.f16.f32 " \
        "{%0,%1,%2,%3}, {%4,%5,%6,%7}, {%8,%9}, {%0,%1,%2,%3};" \
        : "+f"(d[0]), "+f"(d[1]), "+f"(d[2]), "+f"(d[3]) \
        : "r"(a[0]), "r"(a[1]), "r"(a[2]), "r"(a[3]), "r"(b[0]), "r"(b[1]))

// ------------ fused fp32 -> fp16 convert for all 4 source arrays ---------------
__global__ __launch_bounds__(256) void tofp16_all(
    const float* __restrict__ x,  __half* __restrict__ xh,  int nbx,
    const float* __restrict__ w1, __half* __restrict__ w1h, int nbw,
    const float* __restrict__ w2, __half* __restrict__ w2h,
    const float* __restrict__ w3, __half* __restrict__ w3h)
{
    int bx = blockIdx.x;
    const float* src;
    __half* dst;
    if (bx < nbx)            { src = x;  dst = xh;  }
    else if (bx < nbx+nbw)   { src = w1; dst = w1h; bx -= nbx; }
    else if (bx < nbx+2*nbw) { src = w2; dst = w2h; bx -= nbx + nbw; }
    else                     { src = w3; dst = w3h; bx -= nbx + 2*nbw; }
    size_t i = ((size_t)bx * 256 + threadIdx.x) * 4;
    float4 v = *reinterpret_cast<const float4*>(src + i);
    __half2* pd = reinterpret_cast<__half2*>(dst + i);
    pd[0] = __floats2half2_rn(v.x, v.y);
    pd[1] = __floats2half2_rn(v.z, v.w);
}

// -------- FUSED: dual input GEMM (ih + gate) + elementwise + local scan -------
// 128m x 64n tile, 2 CTAs/SM. Each CTA: m-tile = 128 consecutive timesteps of
// one batch, n-tile = 64 h's. Two acc sets (ih, gate), rounded to fp16 into a
// smem (ih,gate) half2 tile, then 128 threads scan two 64-step half-chunks.

#define PART_A 16384               // 128 rows x 128B
#define PART_W 8192                // 64 rows x 128B
#define STAGE3_B (PART_A + 2*PART_W)  // A|W1|W2 = 32KB per stage
#define DYN3 (3*STAGE3_B + 1024)      // 99328
#define SRS 65                     // scan tile row stride in half2 words

__global__ __launch_bounds__(256, 2) void gemm_scan(
    const __half* __restrict__ A,
    const __half* __restrict__ W1, const __half* __restrict__ W2,
    const float* __restrict__ b_ih, const float* __restrict__ b_g,
    const float* __restrict__ log_a,
    __half2* __restrict__ PH, float* __restrict__ cA, float* __restrict__ cB)
{
    const int K = CD;
    extern __shared__ char dyn[];
    const uint32_t tile = (s2u(dyn) + 127u) & ~127u;
    char* gtile = dyn + (int)(tile - s2u(dyn));

    const int tid = threadIdx.x;
    const int n0 = blockIdx.x * 64;
    const int m0 = blockIdx.y * 128;

    const int wid = tid >> 5, lane = tid & 31;
    const int wm = wid >> 2;
    const int wn = wid & 3;

    const __half* Ap  = A  + (size_t)m0 * K;
    const __half* W1p = W1 + (size_t)n0 * K;
    const __half* W2p = W2 + (size_t)n0 * K;

    // A loader: 2 threads/row x 4 chunks; W loader: 4 threads/row x 2 chunks
    const int alr = tid >> 1, alc = (tid & 1) * 4, alsw = alr & 7;
    const int wlr = tid >> 2, wlc = (tid & 3) * 2, wlsw = wlr & 7;

    auto issue = [&](int s) {
        uint32_t sb = tile + (uint32_t)(s % 3) * STAGE3_B;
        int k0 = s * 64;
        {
            const __half* g = Ap + (size_t)alr * K + k0 + alc * 8;
            uint32_t base = sb + alr * 128;
#pragma unroll
            for (int c = 0; c < 4; c++)
                cp16(base + (((alc + c) ^ alsw) << 4), g + c * 8);
        }
        {
            const __half* g1 = W1p + (size_t)wlr * K + k0 + wlc * 8;
            const __half* g2 = W2p + (size_t)wlr * K + k0 + wlc * 8;
            uint32_t b1 = sb + PART_A + wlr * 128;
            uint32_t b2 = sb + PART_A + PART_W + wlr * 128;
#pragma unroll
            for (int c = 0; c < 2; c++) {
                cp16(b1 + (((wlc + c) ^ wlsw) << 4), g1 + c * 8);
                cp16(b2 + (((wlc + c) ^ wlsw) << 4), g2 + c * 8);
            }
        }
        CP_COMMIT();
    };

    const int arow = wm * 64 + (lane & 15);
    const int ahalf = lane >> 4;
    const int asw = arow & 7;
    const int brow = wn * 16 + ((lane >> 4) << 3) + (lane & 7);
    const int bhalf = (lane >> 3) & 1;
    const int bsw = brow & 7;

    float acc1[4][2][4], acc2[4][2][4];
#pragma unroll
    for (int i = 0; i < 4; i++)
#pragma unroll
        for (int j = 0; j < 2; j++)
#pragma unroll
            for (int c = 0; c < 4; c++) { acc1[i][j][c] = 0.f; acc2[i][j][c] = 0.f; }

    issue(0); issue(1);

    const int NIT = K / 64;   // 16
    for (int it = 0; it < NIT; ++it) {
        if (it + 1 < NIT) asm volatile("cp.async.wait_group 1;" ::: "memory");
        else              asm volatile("cp.async.wait_group 0;" ::: "memory");
        __syncthreads();
        if (it + 2 < NIT) issue(it + 2);

        uint32_t sb = tile + (uint32_t)(it % 3) * STAGE3_B;
        uint32_t aA  = sb                     + arow * 128;
        uint32_t aB1 = sb + PART_A            + brow * 128;
        uint32_t aB2 = sb + PART_A + PART_W   + brow * 128;

#pragma unroll
        for (int ks = 0; ks < 4; ks++) {
            const int ac = (2 * ks + ahalf) ^ asw;
            const int bc = (2 * ks + bhalf) ^ bsw;
            uint32_t a[4][4], b1[2][2], b2[2][2];
#pragma unroll
            for (int i = 0; i < 4; i++)
                ldsm4(a[i], aA + i * (16 * 128) + (ac << 4));
            {
                uint32_t rb[4];
                ldsm4(rb, aB1 + (bc << 4));
                b1[0][0] = rb[0]; b1[0][1] = rb[1];
                b1[1][0] = rb[2]; b1[1][1] = rb[3];
                ldsm4(rb, aB2 + (bc << 4));
                b2[0][0] = rb[0]; b2[0][1] = rb[1];
                b2[1][0] = rb[2]; b2[1][1] = rb[3];
            }
#pragma unroll
            for (int i = 0; i < 4; i++)
#pragma unroll
                for (int j = 0; j < 2; j++) {
                    MMA_F16(acc1[i][j], a[i], b1[j]);
                    MMA_F16(acc2[i][j], a[i], b2[j]);
                }
        }
    }
    __syncthreads();   // all smem reads done; reuse pipeline smem for scan tile

    // ---- write (ih, gate) fp16 pairs to smem scan tile: [t 0..127][h 0..63] ---
    __half2* S = reinterpret_cast<__half2*>(gtile);
    const int g = lane >> 2, tq = lane & 3;
#pragma unroll
    for (int i = 0; i < 4; i++) {
        const int r0 = wm * 64 + i * 16 + g;
#pragma unroll
        for (int j = 0; j < 2; j++) {
            const int n = wn * 16 + j * 8 + tq * 2;
            S[r0 * SRS + n]           = __floats2half2_rn(acc1[i][j][0], acc2[i][j][0]);
            S[r0 * SRS + n + 1]       = __floats2half2_rn(acc1[i][j][1], acc2[i][j][1]);
            S[(r0 + 8) * SRS + n]     = __floats2half2_rn(acc1[i][j][2], acc2[i][j][2]);
            S[(r0 + 8) * SRS + n + 1] = __floats2half2_rn(acc1[i][j][3], acc2[i][j][3]);
        }
    }
    __syncthreads();

    // ---- scan: 128 threads = 64 h x 2 half-chunks of 64 timesteps -------------
    if (tid < 128) {
        const int h = tid & 63;
        const int hs = tid >> 6;            // half-chunk 0/1
        const int hg = n0 + h;              // global h
        const float bg = b_g[hg], bi = b_ih[hg], ea = __expf(log_a[hg]);

        float p = 1.f, hl = 0.f;
        size_t grow = ((size_t)(m0 + hs * 64)) * CH + hg;
#pragma unroll 8
        for (int t = 0; t < 64; t++) {
            float2 f = __half22float2(S[(hs * 64 + t) * SRS + h]);
            float gate = 1.f / (1.f + __expf(-(f.y + bg)));
            float beta = gate * (f.x + bi);
            float a = (1.f - gate) * ea;
            hl = fmaf(a, hl, beta);
            p *= a;
            PH[grow + (size_t)t * CH] = __halves2half2(__float2half_rn(p), __float2half_rn(hl));
        }
        const int b = m0 >> 13;               // /CT
        const int c0 = (m0 & (CT - 1)) >> 6;  // /CHUNK
        size_t co = ((size_t)b * NCHUNK + c0 + hs) * CH + hg;
        cA[co] = p;
        cB[co] = hl;
    }
}

// ------------------ single-pass fp16 GEMM (output, single mode) ---------------
#define PART_B 16384
#define STAGE_F16 (2*PART_B)       // A|B = 32KB per stage
#define NSTAGE 3
#define DYN_F16 (NSTAGE*STAGE_F16 + 1024)

__global__ __launch_bounds__(256, 2) void gemm_f16(
    const __half* __restrict__ A, const __half* __restrict__ B,
    const float* __restrict__ bias, float* __restrict__ C,
    int M, int N, int K)
{
    extern __shared__ char dyn[];
    const uint32_t tile = (s2u(dyn) + 127u) & ~127u;

    const int tid = threadIdx.x;
    const int n0 = blockIdx.x * 128;
    const int m0 = blockIdx.y * 128;

    const int wid = tid >> 5, lane = tid & 31;
    const int wm = wid >> 2;
    const int wn = wid & 3;

    const __half* srcs[2] = { A + (size_t)m0 * K, B + (size_t)n0 * K };

    const int lr = tid >> 1;
    const int lc0 = (tid & 1) * 4;
    const int lsw = lr & 7;

    auto issue = [&](int s) {
        uint32_t sb = tile + (uint32_t)(s % NSTAGE) * STAGE_F16;
        int k0 = s * 64;
#pragma unroll
        for (int p = 0; p < 2; p++) {
            const __half* g = srcs[p] + (size_t)lr * K + k0 + lc0 * 8;
            uint32_t base = sb + p * PART_B + lr * 128;
#pragma unroll
            for (int c = 0; c < 4; c++)
                cp16(base + (((lc0 + c) ^ lsw) << 4), g + c * 8);
        }
        CP_COMMIT();
    };

    const int arow = wm * 64 + (lane & 15);
    const int ahalf = lane >> 4;
    const int asw = arow & 7;
    const int brow = wn * 32 + ((lane >> 4) << 3) + (lane & 7);
    const int bhalf = (lane >> 3) & 1;
    const int bsw = brow & 7;

    float acc[4][4][4];
#pragma unroll
    for (int i = 0; i < 4; i++)
#pragma unroll
        for (int j = 0; j < 4; j++)
#pragma unroll
            for (int c = 0; c < 4; c++) acc[i][j][c] = 0.f;

    issue(0); issue(1);

    const int NIT = K / 64;
    for (int it = 0; it < NIT; ++it) {
        if (it + 1 < NIT) asm volatile("cp.async.wait_group 1;" ::: "memory");
        else              asm volatile("cp.async.wait_group 0;" ::: "memory");
        __syncthreads();
        if (it + 2 < NIT) issue(it + 2);

        uint32_t sb = tile + (uint32_t)(it % NSTAGE) * STAGE_F16;
        uint32_t aA = sb          + arow * 128;
        uint32_t aB = sb + PART_B + brow * 128;

#pragma unroll
        for (int ks = 0; ks < 4; ks++) {
            const int ac = (2 * ks + ahalf) ^ asw;
            const int bc = (2 * ks + bhalf) ^ bsw;
            uint32_t a[4][4], b[4][2];
#pragma unroll
            for (int i = 0; i < 4; i++)
                ldsm4(a[i], aA + i * (16 * 128) + (ac << 4));
#pragma unroll
            for (int q = 0; q < 2; q++) {
                uint32_t rb[4];
                ldsm4(rb, aB + q * (16 * 128) + (bc << 4));
                b[q*2+0][0] = rb[0]; b[q*2+0][1] = rb[1];
                b[q*2+1][0] = rb[2]; b[q*2+1][1] = rb[3];
            }
#pragma unroll
            for (int i = 0; i < 4; i++)
#pragma unroll
                for (int j = 0; j < 4; j++)
                    MMA_F16(acc[i][j], a[i], b[j]);
        }
    }

    const int g = lane >> 2, tq = lane & 3;
#pragma unroll
    for (int i = 0; i < 4; i++) {
        const int m = m0 + wm * 64 + i * 16 + g;
#pragma unroll
        for (int j = 0; j < 4; j++) {
            const int n = n0 + wn * 32 + j * 8 + tq * 2;
            float b0 = bias[n], b1 = bias[n + 1];
            float2 v0 = { acc[i][j][0] + b0, acc[i][j][1] + b1 };
            float2 v1 = { acc[i][j][2] + b0, acc[i][j][3] + b1 };
            *reinterpret_cast<float2*>(C + (size_t)m * N + n)       = v0;
            *reinterpret_cast<float2*>(C + (size_t)(m + 8) * N + n) = v1;
        }
    }
}

// ---------------- pass B: scan across chunk summaries per (b,h) ---------------
__global__ __launch_bounds__(256) void scan_carry(
    const float* __restrict__ cA, const float* __restrict__ cB,
    float* __restrict__ pref)
{
    int idx = blockIdx.x * blockDim.x + threadIdx.x;
    int h = idx % CH;
    int b = idx / CH;
    float run = 0.f;
#pragma unroll
    for (int c = 0; c < NCHUNK; c++) {
        size_t o = ((size_t)b * NCHUNK + c) * CH + h;
        pref[o] = run;
        run = fmaf(cA[o], run, cB[o]);
    }
}

// ------- pass C: fixup h = h_local + P*carry, fused LayerNorm -> fp16 ----------
__global__ __launch_bounds__(256) void fix_ln(
    const __half2* __restrict__ PH,
    const float* __restrict__ pref,
    const float* __restrict__ lng, const float* __restrict__ lnb,
    __half* __restrict__ hnh)
{
    __shared__ float sred[16];
    const int row = blockIdx.x;
    const int b = row / CT;
    const int t = row % CT;
    const int c = t / CHUNK;
    const size_t base = (size_t)row * CH;
    const float* prow = pref + ((size_t)b * NCHUNK + c) * CH;
    const int h = threadIdx.x * 4;

    uint4 q = *reinterpret_cast<const uint4*>(PH + base + h);
    float2 q0 = __half22float2(*reinterpret_cast<__half2*>(&q.x));
    float2 q1 = __half22float2(*reinterpret_cast<__half2*>(&q.y));
    float2 q2 = __half22float2(*reinterpret_cast<__half2*>(&q.z));
    float2 q3 = __half22float2(*reinterpret_cast<__half2*>(&q.w));
    float4 pr4 = *reinterpret_cast<const float4*>(prow + h);
    float v[4];
    v[0] = fmaf(q0.x, pr4.x, q0.y);
    v[1] = fmaf(q1.x, pr4.y, q1.y);
    v[2] = fmaf(q2.x, pr4.z, q2.y);
    v[3] = fmaf(q3.x, pr4.w, q3.y);

    float s = v[0] + v[1] + v[2] + v[3];
    float ss = v[0]*v[0] + v[1]*v[1] + v[2]*v[2] + v[3]*v[3];
#pragma unroll
    for (int off = 16; off > 0; off >>= 1) {
        s  += __shfl_xor_sync(0xffffffffu, s,  off);
        ss += __shfl_xor_sync(0xffffffffu, ss, off);
    }
    const int warp = threadIdx.x >> 5, lane = threadIdx.x & 31;
    if (lane == 0) { sred[warp] = s; sred[8 + warp] = ss; }
    __syncthreads();
    if (threadIdx.x < 32) {
        float a  = (lane < 8) ? sred[lane]     : 0.f;
        float b2 = (lane < 8) ? sred[8 + lane] : 0.f;
#pragma unroll
        for (int off = 4; off > 0; off >>= 1) {
            a  += __shfl_xor_sync(0xffffffffu, a,  off);
            b2 += __shfl_xor_sync(0xffffffffu, b2, off);
        }
        if (lane == 0) { sred[0] = a; sred[1] = b2; }
    }
    __syncthreads();
    const float mu  = sred[0] * (1.f / CH);
    const float var = sred[1] * (1.f / CH) - mu * mu;
    const float inv = rsqrtf(var + LN_EPS);

    float4 g4 = *reinterpret_cast<const float4*>(lng + h);
    float4 b4 = *reinterpret_cast<const float4*>(lnb + h);
    float o[4];
    o[0] = (v[0] - mu) * inv * g4.x + b4.x;
    o[1] = (v[1] - mu) * inv * g4.y + b4.y;
    o[2] = (v[2] - mu) * inv * g4.z + b4.z;
    o[3] = (v[3] - mu) * inv * g4.w + b4.w;

    uint2 ou;
    *reinterpret_cast<__half2*>(&ou.x) = __floats2half2_rn(o[0], o[1]);
    *reinterpret_cast<__half2*>(&ou.y) = __floats2half2_rn(o[2], o[3]);
    *reinterpret_cast<uint2*>(hnh + base + h) = ou;
}

// --------------------------------- launcher ----------------------------------
extern "C" void kernel_launch(void* const* d_in, const int* in_sizes, int n_in,
                              void* d_out, int out_size)
{
    const float* x      = (const float*)d_in[0];
    const float* W_ih   = (const float*)d_in[1];
    const float* b_ih   = (const float*)d_in[2];
    const float* log_a  = (const float*)d_in[3];
    const float* W_gate = (const float*)d_in[4];
    const float* b_gate = (const float*)d_in[5];
    const float* W_out  = (const float*)d_in[6];
    const float* b_out  = (const float*)d_in[7];
    const float* ln_g   = (const float*)d_in[8];
    const float* ln_b   = (const float*)d_in[9];
    float* out = (float*)d_out;

    __half *xh, *w1h, *w2h, *w3h, *hnh;
    __half2 *PH;
    float *cA, *cB, *pref;
    cudaGetSymbolAddress((void**)&xh,   g_xh);
    cudaGetSymbolAddress((void**)&w1h,  g_w1h);
    cudaGetSymbolAddress((void**)&w2h,  g_w2h);
    cudaGetSymbolAddress((void**)&w3h,  g_w3h);
    cudaGetSymbolAddress((void**)&hnh,  g_hnh);
    cudaGetSymbolAddress((void**)&PH,   g_PH);
    cudaGetSymbolAddress((void**)&cA,   g_cA);
    cudaGetSymbolAddress((void**)&cB,   g_cB);
    cudaGetSymbolAddress((void**)&pref, g_pref);

    cudaFuncSetAttribute(gemm_scan,
                         cudaFuncAttributeMaxDynamicSharedMemorySize, DYN3);
    cudaFuncSetAttribute(gemm_f16,
                         cudaFuncAttributeMaxDynamicSharedMemorySize, DYN_F16);

    // fused conversions
    const int NBX = (int)((size_t)CM * CD / 4 / 256);
    const int NBW = (int)((size_t)CH * CD / 4 / 256);
    tofp16_all<<<NBX + 3 * NBW, 256>>>(
        x, xh, NBX, W_ih, w1h, NBW, W_gate, w2h, W_out, w3h);

    // fused dual GEMM + elementwise + local scan (128x64 tiles, 2 CTA/SM)
    gemm_scan<<<dim3(CH / 64, CM / 128), 256, DYN3>>>(
        xh, w1h, w2h, b_ih, b_gate, log_a, PH, cA, cB);

    scan_carry<<<(CB * CH) / 256, 256>>>(cA, cB, pref);
    fix_ln<<<CM, 256>>>(PH, pref, ln_g, ln_b, hnh);

    // output GEMM
    gemm_f16<<<dim3(CO / 128, CM / 128), 256, DYN_F16>>>(
        hnh, w3h, b_out, out, CM, CO, CH);
}

// round 16
// speedup vs baseline: 1.1601x; 1.0118x over previous
#include <cuda_runtime.h>
#include <cuda_fp16.h>
#include <cstdint>

// Problem constants (fixed shapes from reference)
#define CB 4
#define CT 8192
#define CD 1024
#define CH 1024
#define CO 1024
#define CM (CB*CT)    // 32768 rows
#define NCHUNK 128
#define CHUNK (CT/NCHUNK)   // 64
#define LN_EPS 1e-5f

// ---------------- scratch (device globals; no allocation allowed) -------------
__device__ __half g_xh[(size_t)CM*CD];
__device__ __half g_w1h[(size_t)CH*CD], g_w2h[(size_t)CH*CD];
__device__ __half g_w3h[(size_t)CO*CH];
__device__ __half2 g_PH[(size_t)CM*CH];   // interleaved (prefix-prod, local-h)
__device__ __half g_hnh[(size_t)CM*CH];
__device__ float g_cA[CB*NCHUNK*CH];
__device__ float g_cB[CB*NCHUNK*CH];
__device__ float g_pref[CB*NCHUNK*CH];

// ------------------------------ helpers ---------------------------------------
__device__ __forceinline__ uint32_t s2u(const void* p) {
    return (uint32_t)__cvta_generic_to_shared(p);
}
__device__ __forceinline__ void cp16(uint32_t s, const void* g) {
    asm volatile("cp.async.cg.shared.global [%0], [%1], 16;" :: "r"(s), "l"(g));
}
#define CP_COMMIT() asm volatile("cp.async.commit_group;" ::: "memory")

__device__ __forceinline__ void ldsm4(uint32_t* r, uint32_t addr) {
    asm volatile("ldmatrix.sync.aligned.m8n8.x4.shared.b16 {%0,%1,%2,%3}, [%4];"
        : "=r"(r[0]), "=r"(r[1]), "=r"(r[2]), "=r"(r[3]) : "r"(addr));
}

#define MMA_F16(d, a, b) \
    asm volatile("mma.sync.aligned.m16n8k16.row.col.f32.f16.f16.f32 " \
        "{%0,%1,%2,%3}, {%4,%5,%6,%7}, {%8,%9}, {%0,%1,%2,%3};" \
        : "+f"(d[0]), "+f"(d[1]), "+f"(d[2]), "+f"(d[3]) \
        : "r"(a[0]), "r"(a[1]), "r"(a[2]), "r"(a[3]), "r"(b[0]), "r"(b[1]))

// ------------ fused fp32 -> fp16 convert for all 4 source arrays ---------------
__global__ __launch_bounds__(256) void tofp16_all(
    const float* __restrict__ x,  __half* __restrict__ xh,  int nbx,
    const float* __restrict__ w1, __half* __restrict__ w1h, int nbw,
    const float* __restrict__ w2, __half* __restrict__ w2h,
    const float* __restrict__ w3, __half* __restrict__ w3h)
{
    int bx = blockIdx.x;
    const float* src;
    __half* dst;
    if (bx < nbx)            { src = x;  dst = xh;  }
    else if (bx < nbx+nbw)   { src = w1; dst = w1h; bx -= nbx; }
    else if (bx < nbx+2*nbw) { src = w2; dst = w2h; bx -= nbx + nbw; }
    else                     { src = w3; dst = w3h; bx -= nbx + 2*nbw; }
    size_t i = ((size_t)bx * 256 + threadIdx.x) * 4;
    float4 v = *reinterpret_cast<const float4*>(src + i);
    uint2 o;
    *reinterpret_cast<__half2*>(&o.x) = __floats2half2_rn(v.x, v.y);
    *reinterpret_cast<__half2*>(&o.y) = __floats2half2_rn(v.z, v.w);
    *reinterpret_cast<uint2*>(dst + i) = o;
}

// -------- FUSED: dual input GEMM (ih + gate) + elementwise + local scan -------
// 128m x 64n tile, 2 CTAs/SM. Each CTA: m-tile = 128 consecutive timesteps of
// one batch, n-tile = 64 h's. Two acc sets (ih, gate), rounded to fp16 into a
// smem (ih,gate) half2 tile, then 128 threads scan two 64-step half-chunks.

#define PART_A 16384               // 128 rows x 128B
#define PART_W 8192                // 64 rows x 128B
#define STAGE3_B (PART_A + 2*PART_W)  // A|W1|W2 = 32KB per stage
#define DYN3 (3*STAGE3_B + 1024)      // 99328
#define SRS 65                     // scan tile row stride in half2 words

__global__ __launch_bounds__(256, 2) void gemm_scan(
    const __half* __restrict__ A,
    const __half* __restrict__ W1, const __half* __restrict__ W2,
    const float* __restrict__ b_ih, const float* __restrict__ b_g,
    const float* __restrict__ log_a,
    __half2* __restrict__ PH, float* __restrict__ cA, float* __restrict__ cB)
{
    const int K = CD;
    extern __shared__ char dyn[];
    const uint32_t tile = (s2u(dyn) + 127u) & ~127u;
    char* gtile = dyn + (int)(tile - s2u(dyn));

    const int tid = threadIdx.x;
    const int n0 = blockIdx.x * 64;
    const int m0 = blockIdx.y * 128;

    const int wid = tid >> 5, lane = tid & 31;
    const int wm = wid >> 2;
    const int wn = wid & 3;

    const __half* Ap  = A  + (size_t)m0 * K;
    const __half* W1p = W1 + (size_t)n0 * K;
    const __half* W2p = W2 + (size_t)n0 * K;

    const int alr = tid >> 1, alc = (tid & 1) * 4, alsw = alr & 7;
    const int wlr = tid >> 2, wlc = (tid & 3) * 2, wlsw = wlr & 7;

    auto issue = [&](int s) {
        uint32_t sb = tile + (uint32_t)(s % 3) * STAGE3_B;
        int k0 = s * 64;
        {
            const __half* g = Ap + (size_t)alr * K + k0 + alc * 8;
            uint32_t base = sb + alr * 128;
#pragma unroll
            for (int c = 0; c < 4; c++)
                cp16(base + (((alc + c) ^ alsw) << 4), g + c * 8);
        }
        {
            const __half* g1 = W1p + (size_t)wlr * K + k0 + wlc * 8;
            const __half* g2 = W2p + (size_t)wlr * K + k0 + wlc * 8;
            uint32_t b1 = sb + PART_A + wlr * 128;
            uint32_t b2 = sb + PART_A + PART_W + wlr * 128;
#pragma unroll
            for (int c = 0; c < 2; c++) {
                cp16(b1 + (((wlc + c) ^ wlsw) << 4), g1 + c * 8);
                cp16(b2 + (((wlc + c) ^ wlsw) << 4), g2 + c * 8);
            }
        }
        CP_COMMIT();
    };

    const int arow = wm * 64 + (lane & 15);
    const int ahalf = lane >> 4;
    const int asw = arow & 7;
    const int brow = wn * 16 + ((lane >> 4) << 3) + (lane & 7);
    const int bhalf = (lane >> 3) & 1;
    const int bsw = brow & 7;

    float acc1[4][2][4], acc2[4][2][4];
#pragma unroll
    for (int i = 0; i < 4; i++)
#pragma unroll
        for (int j = 0; j < 2; j++)
#pragma unroll
            for (int c = 0; c < 4; c++) { acc1[i][j][c] = 0.f; acc2[i][j][c] = 0.f; }

    issue(0); issue(1);

    const int NIT = K / 64;   // 16
    for (int it = 0; it < NIT; ++it) {
        if (it + 1 < NIT) asm volatile("cp.async.wait_group 1;" ::: "memory");
        else              asm volatile("cp.async.wait_group 0;" ::: "memory");
        __syncthreads();
        if (it + 2 < NIT) issue(it + 2);

        uint32_t sb = tile + (uint32_t)(it % 3) * STAGE3_B;
        uint32_t aA  = sb                     + arow * 128;
        uint32_t aB1 = sb + PART_A            + brow * 128;
        uint32_t aB2 = sb + PART_A + PART_W   + brow * 128;

#pragma unroll
        for (int ks = 0; ks < 4; ks++) {
            const int ac = (2 * ks + ahalf) ^ asw;
            const int bc = (2 * ks + bhalf) ^ bsw;
            uint32_t a[4][4], b1[2][2], b2[2][2];
#pragma unroll
            for (int i = 0; i < 4; i++)
                ldsm4(a[i], aA + i * (16 * 128) + (ac << 4));
            {
                uint32_t rb[4];
                ldsm4(rb, aB1 + (bc << 4));
                b1[0][0] = rb[0]; b1[0][1] = rb[1];
                b1[1][0] = rb[2]; b1[1][1] = rb[3];
                ldsm4(rb, aB2 + (bc << 4));
                b2[0][0] = rb[0]; b2[0][1] = rb[1];
                b2[1][0] = rb[2]; b2[1][1] = rb[3];
            }
#pragma unroll
            for (int i = 0; i < 4; i++)
#pragma unroll
                for (int j = 0; j < 2; j++) {
                    MMA_F16(acc1[i][j], a[i], b1[j]);
                    MMA_F16(acc2[i][j], a[i], b2[j]);
                }
        }
    }
    __syncthreads();   // all smem reads done; reuse pipeline smem for scan tile

    // ---- write (ih, gate) fp16 pairs to smem scan tile: [t 0..127][h 0..63] ---
    __half2* S = reinterpret_cast<__half2*>(gtile);
    const int g = lane >> 2, tq = lane & 3;
#pragma unroll
    for (int i = 0; i < 4; i++) {
        const int r0 = wm * 64 + i * 16 + g;
#pragma unroll
        for (int j = 0; j < 2; j++) {
            const int n = wn * 16 + j * 8 + tq * 2;
            S[r0 * SRS + n]           = __floats2half2_rn(acc1[i][j][0], acc2[i][j][0]);
            S[r0 * SRS + n + 1]       = __floats2half2_rn(acc1[i][j][1], acc2[i][j][1]);
            S[(r0 + 8) * SRS + n]     = __floats2half2_rn(acc1[i][j][2], acc2[i][j][2]);
            S[(r0 + 8) * SRS + n + 1] = __floats2half2_rn(acc1[i][j][3], acc2[i][j][3]);
        }
    }
    __syncthreads();

    // ---- scan: 128 threads = 64 h x 2 half-chunks of 64 timesteps -------------
    if (tid < 128) {
        const int h = tid & 63;
        const int hs = tid >> 6;            // half-chunk 0/1
        const int hg = n0 + h;              // global h
        const float bg = b_g[hg], bi = b_ih[hg], ea = __expf(log_a[hg]);

        float p = 1.f, hl = 0.f;
        size_t grow = ((size_t)(m0 + hs * 64)) * CH + hg;
#pragma unroll 8
        for (int t = 0; t < 64; t++) {
            float2 f = __half22float2(S[(hs * 64 + t) * SRS + h]);
            float gate = 1.f / (1.f + __expf(-(f.y + bg)));
            float beta = gate * (f.x + bi);
            float a = (1.f - gate) * ea;
            hl = fmaf(a, hl, beta);
            p *= a;
            PH[grow + (size_t)t * CH] = __halves2half2(__float2half_rn(p), __float2half_rn(hl));
        }
        const int b = m0 >> 13;               // /CT
        const int c0 = (m0 & (CT - 1)) >> 6;  // /CHUNK
        size_t co = ((size_t)b * NCHUNK + c0 + hs) * CH + hg;
        cA[co] = p;
        cB[co] = hl;
    }
}

// ------------------ single-pass fp16 GEMM (output, single mode) ---------------
#define PART_B 16384
#define STAGE_F16 (2*PART_B)       // A|B = 32KB per stage
#define NSTAGE 3
#define DYN_F16 (NSTAGE*STAGE_F16 + 1024)

__global__ __launch_bounds__(256, 2) void gemm_f16(
    const __half* __restrict__ A, const __half* __restrict__ B,
    const float* __restrict__ bias, float* __restrict__ C,
    int M, int N, int K)
{
    extern __shared__ char dyn[];
    const uint32_t tile = (s2u(dyn) + 127u) & ~127u;

    const int tid = threadIdx.x;
    const int n0 = blockIdx.x * 128;
    const int m0 = blockIdx.y * 128;

    const int wid = tid >> 5, lane = tid & 31;
    const int wm = wid >> 2;
    const int wn = wid & 3;

    const __half* srcs[2] = { A + (size_t)m0 * K, B + (size_t)n0 * K };

    const int lr = tid >> 1;
    const int lc0 = (tid & 1) * 4;
    const int lsw = lr & 7;

    auto issue = [&](int s) {
        uint32_t sb = tile + (uint32_t)(s % NSTAGE) * STAGE_F16;
        int k0 = s * 64;
#pragma unroll
        for (int p = 0; p < 2; p++) {
            const __half* g = srcs[p] + (size_t)lr * K + k0 + lc0 * 8;
            uint32_t base = sb + p * PART_B + lr * 128;
#pragma unroll
            for (int c = 0; c < 4; c++)
                cp16(base + (((lc0 + c) ^ lsw) << 4), g + c * 8);
        }
        CP_COMMIT();
    };

    const int arow = wm * 64 + (lane & 15);
    const int ahalf = lane >> 4;
    const int asw = arow & 7;
    const int brow = wn * 32 + ((lane >> 4) << 3) + (lane & 7);
    const int bhalf = (lane >> 3) & 1;
    const int bsw = brow & 7;

    float acc[4][4][4];
#pragma unroll
    for (int i = 0; i < 4; i++)
#pragma unroll
        for (int j = 0; j < 4; j++)
#pragma unroll
            for (int c = 0; c < 4; c++) acc[i][j][c] = 0.f;

    issue(0); issue(1);

    const int NIT = K / 64;
    for (int it = 0; it < NIT; ++it) {
        if (it + 1 < NIT) asm volatile("cp.async.wait_group 1;" ::: "memory");
        else              asm volatile("cp.async.wait_group 0;" ::: "memory");
        __syncthreads();
        if (it + 2 < NIT) issue(it + 2);

        uint32_t sb = tile + (uint32_t)(it % NSTAGE) * STAGE_F16;
        uint32_t aA = sb          + arow * 128;
        uint32_t aB = sb + PART_B + brow * 128;

#pragma unroll
        for (int ks = 0; ks < 4; ks++) {
            const int ac = (2 * ks + ahalf) ^ asw;
            const int bc = (2 * ks + bhalf) ^ bsw;
            uint32_t a[4][4], b[4][2];
#pragma unroll
            for (int i = 0; i < 4; i++)
                ldsm4(a[i], aA + i * (16 * 128) + (ac << 4));
#pragma unroll
            for (int q = 0; q < 2; q++) {
                uint32_t rb[4];
                ldsm4(rb, aB + q * (16 * 128) + (bc << 4));
                b[q*2+0][0] = rb[0]; b[q*2+0][1] = rb[1];
                b[q*2+1][0] = rb[2]; b[q*2+1][1] = rb[3];
            }
#pragma unroll
            for (int i = 0; i < 4; i++)
#pragma unroll
                for (int j = 0; j < 4; j++)
                    MMA_F16(acc[i][j], a[i], b[j]);
        }
    }

    const int g = lane >> 2, tq = lane & 3;
#pragma unroll
    for (int i = 0; i < 4; i++) {
        const int m = m0 + wm * 64 + i * 16 + g;
#pragma unroll
        for (int j = 0; j < 4; j++) {
            const int n = n0 + wn * 32 + j * 8 + tq * 2;
            float b0 = bias[n], b1 = bias[n + 1];
            float2 v0 = { acc[i][j][0] + b0, acc[i][j][1] + b1 };
            float2 v1 = { acc[i][j][2] + b0, acc[i][j][3] + b1 };
            *reinterpret_cast<float2*>(C + (size_t)m * N + n)       = v0;
            *reinterpret_cast<float2*>(C + (size_t)(m + 8) * N + n) = v1;
        }
    }
}

// ----- pass B: warp-parallel affine scan across 128 chunk summaries ------------
// One warp per (b,h); lane l composes chunks [4l, 4l+4), shfl_up inclusive scan
// of affine composites (A,B), then exclusive prefix -> pref for each chunk.
__global__ __launch_bounds__(256) void scan_carry(
    const float* __restrict__ cA, const float* __restrict__ cB,
    float* __restrict__ pref)
{
    const int gw = (blockIdx.x * 256 + threadIdx.x) >> 5;   // warp id 0..4095
    const int lane = threadIdx.x & 31;
    const int h = gw % CH;
    const int b = gw / CH;
    const size_t base = (size_t)b * NCHUNK * CH + h;

    float a[4], v[4];
#pragma unroll
    for (int i = 0; i < 4; i++) {
        size_t o = base + (size_t)(lane * 4 + i) * CH;
        a[i] = cA[o];
        v[i] = cB[o];
    }
    // lane-local composite (chunks applied in time order)
    float A = a[0], B = v[0];
#pragma unroll
    for (int i = 1; i < 4; i++) {
        B = fmaf(a[i], B, v[i]);
        A = a[i] * A;
    }
    // inclusive warp scan of composites: cur = cur ∘ prev
#pragma unroll
    for (int off = 1; off < 32; off <<= 1) {
        float Ap = __shfl_up_sync(0xffffffffu, A, off);
        float Bp = __shfl_up_sync(0xffffffffu, B, off);
        if (lane >= off) {
            B = fmaf(A, Bp, B);
            A = A * Ap;
        }
    }
    // exclusive prefix (state before this lane's chunks); h0 = 0 -> state = B
    float Be = __shfl_up_sync(0xffffffffu, B, 1);
    float run = (lane == 0) ? 0.f : Be;
#pragma unroll
    for (int i = 0; i < 4; i++) {
        size_t o = base + (size_t)(lane * 4 + i) * CH;
        pref[o] = run;
        run = fmaf(a[i], run, v[i]);
    }
}

// ------- pass C: fixup h = h_local + P*carry, fused LayerNorm -> fp16 ----------
__global__ __launch_bounds__(256) void fix_ln(
    const __half2* __restrict__ PH,
    const float* __restrict__ pref,
    const float* __restrict__ lng, const float* __restrict__ lnb,
    __half* __restrict__ hnh)
{
    __shared__ float sred[16];
    const int row = blockIdx.x;
    const int b = row / CT;
    const int t = row % CT;
    const int c = t / CHUNK;
    const size_t base = (size_t)row * CH;
    const float* prow = pref + ((size_t)b * NCHUNK + c) * CH;
    const int h = threadIdx.x * 4;

    uint4 q = *reinterpret_cast<const uint4*>(PH + base + h);
    float2 q0 = __half22float2(*reinterpret_cast<__half2*>(&q.x));
    float2 q1 = __half22float2(*reinterpret_cast<__half2*>(&q.y));
    float2 q2 = __half22float2(*reinterpret_cast<__half2*>(&q.z));
    float2 q3 = __half22float2(*reinterpret_cast<__half2*>(&q.w));
    float4 pr4 = *reinterpret_cast<const float4*>(prow + h);
    float v[4];
    v[0] = fmaf(q0.x, pr4.x, q0.y);
    v[1] = fmaf(q1.x, pr4.y, q1.y);
    v[2] = fmaf(q2.x, pr4.z, q2.y);
    v[3] = fmaf(q3.x, pr4.w, q3.y);

    float s = v[0] + v[1] + v[2] + v[3];
    float ss = v[0]*v[0] + v[1]*v[1] + v[2]*v[2] + v[3]*v[3];
#pragma unroll
    for (int off = 16; off > 0; off >>= 1) {
        s  += __shfl_xor_sync(0xffffffffu, s,  off);
        ss += __shfl_xor_sync(0xffffffffu, ss, off);
    }
    const int warp = threadIdx.x >> 5, lane = threadIdx.x & 31;
    if (lane == 0) { sred[warp] = s; sred[8 + warp] = ss; }
    __syncthreads();
    if (threadIdx.x < 32) {
        float a  = (lane < 8) ? sred[lane]     : 0.f;
        float b2 = (lane < 8) ? sred[8 + lane] : 0.f;
#pragma unroll
        for (int off = 4; off > 0; off >>= 1) {
            a  += __shfl_xor_sync(0xffffffffu, a,  off);
            b2 += __shfl_xor_sync(0xffffffffu, b2, off);
        }
        if (lane == 0) { sred[0] = a; sred[1] = b2; }
    }
    __syncthreads();
    const float mu  = sred[0] * (1.f / CH);
    const float var = sred[1] * (1.f / CH) - mu * mu;
    const float inv = rsqrtf(var + LN_EPS);

    float4 g4 = *reinterpret_cast<const float4*>(lng + h);
    float4 b4 = *reinterpret_cast<const float4*>(lnb + h);
    float o[4];
    o[0] = (v[0] - mu) * inv * g4.x + b4.x;
    o[1] = (v[1] - mu) * inv * g4.y + b4.y;
    o[2] = (v[2] - mu) * inv * g4.z + b4.z;
    o[3] = (v[3] - mu) * inv * g4.w + b4.w;

    uint2 ou;
    *reinterpret_cast<__half2*>(&ou.x) = __floats2half2_rn(o[0], o[1]);
    *reinterpret_cast<__half2*>(&ou.y) = __floats2half2_rn(o[2], o[3]);
    *reinterpret_cast<uint2*>(hnh + base + h) = ou;
}

// --------------------------------- launcher ----------------------------------
extern "C" void kernel_launch(void* const* d_in, const int* in_sizes, int n_in,
                              void* d_out, int out_size)
{
    const float* x      = (const float*)d_in[0];
    const float* W_ih   = (const float*)d_in[1];
    const float* b_ih   = (const float*)d_in[2];
    const float* log_a  = (const float*)d_in[3];
    const float* W_gate = (const float*)d_in[4];
    const float* b_gate = (const float*)d_in[5];
    const float* W_out  = (const float*)d_in[6];
    const float* b_out  = (const float*)d_in[7];
    const float* ln_g   = (const float*)d_in[8];
    const float* ln_b   = (const float*)d_in[9];
    float* out = (float*)d_out;

    __half *xh, *w1h, *w2h, *w3h, *hnh;
    __half2 *PH;
    float *cA, *cB, *pref;
    cudaGetSymbolAddress((void**)&xh,   g_xh);
    cudaGetSymbolAddress((void**)&w1h,  g_w1h);
    cudaGetSymbolAddress((void**)&w2h,  g_w2h);
    cudaGetSymbolAddress((void**)&w3h,  g_w3h);
    cudaGetSymbolAddress((void**)&hnh,  g_hnh);
    cudaGetSymbolAddress((void**)&PH,   g_PH);
    cudaGetSymbolAddress((void**)&cA,   g_cA);
    cudaGetSymbolAddress((void**)&cB,   g_cB);
    cudaGetSymbolAddress((void**)&pref, g_pref);

    cudaFuncSetAttribute(gemm_scan,
                         cudaFuncAttributeMaxDynamicSharedMemorySize, DYN3);
    cudaFuncSetAttribute(gemm_f16,
                         cudaFuncAttributeMaxDynamicSharedMemorySize, DYN_F16);

    // fused conversions
    const int NBX = (int)((size_t)CM * CD / 4 / 256);
    const int NBW = (int)((size_t)CH * CD / 4 / 256);
    tofp16_all<<<NBX + 3 * NBW, 256>>>(
        x, xh, NBX, W_ih, w1h, NBW, W_gate, w2h, W_out, w3h);

    // fused dual GEMM + elementwise + local scan (128x64 tiles, 2 CTA/SM)
    gemm_scan<<<dim3(CH / 64, CM / 128), 256, DYN3>>>(
        xh, w1h, w2h, b_ih, b_gate, log_a, PH, cA, cB);

    // warp-parallel chunk-carry scan: CB*CH warps = 4096 warps = 512 blocks
    scan_carry<<<(CB * CH * 32) / 256, 256>>>(cA, cB, pref);
    fix_ln<<<CM, 256>>>(PH, pref, ln_g, ln_b, hnh);

    // output GEMM
    gemm_f16<<<dim3(CO / 128, CM / 128), 256, DYN_F16>>>(
        hnh, w3h, b_out, out, CM, CO, CH);
}

// round 17
// speedup vs baseline: 1.1791x; 1.0164x over previous
#include <cuda_runtime.h>
#include <cuda_fp16.h>
#include <cstdint>

// Problem constants (fixed shapes from reference)
#define CB 4
#define CT 8192
#define CD 1024
#define CH 1024
#define CO 1024
#define CM (CB*CT)    // 32768 rows
#define NCHUNK 128
#define CHUNK (CT/NCHUNK)   // 64
#define LN_EPS 1e-5f

// ---------------- scratch (device globals; no allocation allowed) -------------
__device__ __half g_xh[(size_t)CM*CD];
__device__ __half g_w1h[(size_t)CH*CD], g_w2h[(size_t)CH*CD];
__device__ __half g_w3h[(size_t)CO*CH];
__device__ __half2 g_PH[(size_t)CM*CH];   // interleaved (prefix-prod, local-h)
__device__ __half g_hnh[(size_t)CM*CH];
__device__ float g_cA[CB*NCHUNK*CH];
__device__ float g_cB[CB*NCHUNK*CH];
__device__ float g_pref[CB*NCHUNK*CH];

// ------------------------------ helpers ---------------------------------------
__device__ __forceinline__ uint32_t s2u(const void* p) {
    return (uint32_t)__cvta_generic_to_shared(p);
}
__device__ __forceinline__ void cp16(uint32_t s, const void* g) {
    asm volatile("cp.async.cg.shared.global [%0], [%1], 16;" :: "r"(s), "l"(g));
}
#define CP_COMMIT() asm volatile("cp.async.commit_group;" ::: "memory")

__device__ __forceinline__ void ldsm4(uint32_t* r, uint32_t addr) {
    asm volatile("ldmatrix.sync.aligned.m8n8.x4.shared.b16 {%0,%1,%2,%3}, [%4];"
        : "=r"(r[0]), "=r"(r[1]), "=r"(r[2]), "=r"(r[3]) : "r"(addr));
}

#define MMA_F16(d, a, b) \
    asm volatile("mma.sync.aligned.m16n8k16.row.col.f32.f16.f16.f32 " \
        "{%0,%1,%2,%3}, {%4,%5,%6,%7}, {%8,%9}, {%0,%1,%2,%3};" \
        : "+f"(d[0]), "+f"(d[1]), "+f"(d[2]), "+f"(d[3]) \
        : "r"(a[0]), "r"(a[1]), "r"(a[2]), "r"(a[3]), "r"(b[0]), "r"(b[1]))

// ------------ fused fp32 -> fp16 convert for all 4 source arrays ---------------
__global__ __launch_bounds__(256) void tofp16_all(
    const float* __restrict__ x,  __half* __restrict__ xh,  int nbx,
    const float* __restrict__ w1, __half* __restrict__ w1h, int nbw,
    const float* __restrict__ w2, __half* __restrict__ w2h,
    const float* __restrict__ w3, __half* __restrict__ w3h)
{
    int bx = blockIdx.x;
    const float* src;
    __half* dst;
    if (bx < nbx)            { src = x;  dst = xh;  }
    else if (bx < nbx+nbw)   { src = w1; dst = w1h; bx -= nbx; }
    else if (bx < nbx+2*nbw) { src = w2; dst = w2h; bx -= nbx + nbw; }
    else                     { src = w3; dst = w3h; bx -= nbx + 2*nbw; }
    size_t i = ((size_t)bx * 256 + threadIdx.x) * 4;
    float4 v = *reinterpret_cast<const float4*>(src + i);
    uint2 o;
    *reinterpret_cast<__half2*>(&o.x) = __floats2half2_rn(v.x, v.y);
    *reinterpret_cast<__half2*>(&o.y) = __floats2half2_rn(v.z, v.w);
    *reinterpret_cast<uint2*>(dst + i) = o;
}

// -------- FUSED: dual input GEMM (ih + gate) + elementwise + local scan -------
#define PART_A 16384               // 128 rows x 128B
#define PART_W 8192                // 64 rows x 128B
#define STAGE3_B (PART_A + 2*PART_W)  // A|W1|W2 = 32KB per stage
#define DYN3 (3*STAGE3_B + 1024)      // 99328
#define SRS 65                     // scan tile row stride in half2 words

__global__ __launch_bounds__(256, 2) void gemm_scan(
    const __half* __restrict__ A,
    const __half* __restrict__ W1, const __half* __restrict__ W2,
    const float* __restrict__ b_ih, const float* __restrict__ b_g,
    const float* __restrict__ log_a,
    __half2* __restrict__ PH, float* __restrict__ cA, float* __restrict__ cB)
{
    const int K = CD;
    extern __shared__ char dyn[];
    const uint32_t tile = (s2u(dyn) + 127u) & ~127u;
    char* gtile = dyn + (int)(tile - s2u(dyn));

    const int tid = threadIdx.x;
    const int n0 = blockIdx.x * 64;
    const int m0 = blockIdx.y * 128;

    const int wid = tid >> 5, lane = tid & 31;
    const int wm = wid >> 2;
    const int wn = wid & 3;

    const __half* Ap  = A  + (size_t)m0 * K;
    const __half* W1p = W1 + (size_t)n0 * K;
    const __half* W2p = W2 + (size_t)n0 * K;

    const int alr = tid >> 1, alc = (tid & 1) * 4, alsw = alr & 7;
    const int wlr = tid >> 2, wlc = (tid & 3) * 2, wlsw = wlr & 7;

    auto issue = [&](int s) {
        uint32_t sb = tile + (uint32_t)(s % 3) * STAGE3_B;
        int k0 = s * 64;
        {
            const __half* g = Ap + (size_t)alr * K + k0 + alc * 8;
            uint32_t base = sb + alr * 128;
#pragma unroll
            for (int c = 0; c < 4; c++)
                cp16(base + (((alc + c) ^ alsw) << 4), g + c * 8);
        }
        {
            const __half* g1 = W1p + (size_t)wlr * K + k0 + wlc * 8;
            const __half* g2 = W2p + (size_t)wlr * K + k0 + wlc * 8;
            uint32_t b1 = sb + PART_A + wlr * 128;
            uint32_t b2 = sb + PART_A + PART_W + wlr * 128;
#pragma unroll
            for (int c = 0; c < 2; c++) {
                cp16(b1 + (((wlc + c) ^ wlsw) << 4), g1 + c * 8);
                cp16(b2 + (((wlc + c) ^ wlsw) << 4), g2 + c * 8);
            }
        }
        CP_COMMIT();
    };

    const int arow = wm * 64 + (lane & 15);
    const int ahalf = lane >> 4;
    const int asw = arow & 7;
    const int brow = wn * 16 + ((lane >> 4) << 3) + (lane & 7);
    const int bhalf = (lane >> 3) & 1;
    const int bsw = brow & 7;

    float acc1[4][2][4], acc2[4][2][4];
#pragma unroll
    for (int i = 0; i < 4; i++)
#pragma unroll
        for (int j = 0; j < 2; j++)
#pragma unroll
            for (int c = 0; c < 4; c++) { acc1[i][j][c] = 0.f; acc2[i][j][c] = 0.f; }

    issue(0); issue(1);

    const int NIT = K / 64;   // 16
    for (int it = 0; it < NIT; ++it) {
        if (it + 1 < NIT) asm volatile("cp.async.wait_group 1;" ::: "memory");
        else              asm volatile("cp.async.wait_group 0;" ::: "memory");
        __syncthreads();
        if (it + 2 < NIT) issue(it + 2);

        uint32_t sb = tile + (uint32_t)(it % 3) * STAGE3_B;
        uint32_t aA  = sb                     + arow * 128;
        uint32_t aB1 = sb + PART_A            + brow * 128;
        uint32_t aB2 = sb + PART_A + PART_W   + brow * 128;

#pragma unroll
        for (int ks = 0; ks < 4; ks++) {
            const int ac = (2 * ks + ahalf) ^ asw;
            const int bc = (2 * ks + bhalf) ^ bsw;
            uint32_t a[4][4], b1[2][2], b2[2][2];
#pragma unroll
            for (int i = 0; i < 4; i++)
                ldsm4(a[i], aA + i * (16 * 128) + (ac << 4));
            {
                uint32_t rb[4];
                ldsm4(rb, aB1 + (bc << 4));
                b1[0][0] = rb[0]; b1[0][1] = rb[1];
                b1[1][0] = rb[2]; b1[1][1] = rb[3];
                ldsm4(rb, aB2 + (bc << 4));
                b2[0][0] = rb[0]; b2[0][1] = rb[1];
                b2[1][0] = rb[2]; b2[1][1] = rb[3];
            }
#pragma unroll
            for (int i = 0; i < 4; i++)
#pragma unroll
                for (int j = 0; j < 2; j++) {
                    MMA_F16(acc1[i][j], a[i], b1[j]);
                    MMA_F16(acc2[i][j], a[i], b2[j]);
                }
        }
    }
    __syncthreads();   // all smem reads done; reuse pipeline smem for scan tile

    // ---- write (ih, gate) fp16 pairs to smem scan tile: [t 0..127][h 0..63] ---
    __half2* S = reinterpret_cast<__half2*>(gtile);
    const int g = lane >> 2, tq = lane & 3;
#pragma unroll
    for (int i = 0; i < 4; i++) {
        const int r0 = wm * 64 + i * 16 + g;
#pragma unroll
        for (int j = 0; j < 2; j++) {
            const int n = wn * 16 + j * 8 + tq * 2;
            S[r0 * SRS + n]           = __floats2half2_rn(acc1[i][j][0], acc2[i][j][0]);
            S[r0 * SRS + n + 1]       = __floats2half2_rn(acc1[i][j][1], acc2[i][j][1]);
            S[(r0 + 8) * SRS + n]     = __floats2half2_rn(acc1[i][j][2], acc2[i][j][2]);
            S[(r0 + 8) * SRS + n + 1] = __floats2half2_rn(acc1[i][j][3], acc2[i][j][3]);
        }
    }
    __syncthreads();

    // ---- scan: 128 threads = 64 h x 2 half-chunks of 64 timesteps -------------
    if (tid < 128) {
        const int h = tid & 63;
        const int hs = tid >> 6;            // half-chunk 0/1
        const int hg = n0 + h;              // global h
        const float bg = b_g[hg], bi = b_ih[hg], ea = __expf(log_a[hg]);

        float p = 1.f, hl = 0.f;
        size_t grow = ((size_t)(m0 + hs * 64)) * CH + hg;
#pragma unroll 8
        for (int t = 0; t < 64; t++) {
            float2 f = __half22float2(S[(hs * 64 + t) * SRS + h]);
            float gate = 1.f / (1.f + __expf(-(f.y + bg)));
            float beta = gate * (f.x + bi);
            float a = (1.f - gate) * ea;
            hl = fmaf(a, hl, beta);
            p *= a;
            PH[grow + (size_t)t * CH] = __halves2half2(__float2half_rn(p), __float2half_rn(hl));
        }
        const int b = m0 >> 13;               // /CT
        const int c0 = (m0 & (CT - 1)) >> 6;  // /CHUNK
        size_t co = ((size_t)b * NCHUNK + c0 + hs) * CH + hg;
        cA[co] = p;
        cB[co] = hl;
    }
}

// ------------------ single-pass fp16 GEMM (output, single mode) ---------------
#define PART_B 16384
#define STAGE_F16 (2*PART_B)       // A|B = 32KB per stage
#define NSTAGE 3
#define DYN_F16 (NSTAGE*STAGE_F16 + 1024)

__global__ __launch_bounds__(256, 2) void gemm_f16(
    const __half* __restrict__ A, const __half* __restrict__ B,
    const float* __restrict__ bias, float* __restrict__ C,
    int M, int N, int K)
{
    extern __shared__ char dyn[];
    const uint32_t tile = (s2u(dyn) + 127u) & ~127u;

    const int tid = threadIdx.x;
    const int n0 = blockIdx.x * 128;
    const int m0 = blockIdx.y * 128;

    const int wid = tid >> 5, lane = tid & 31;
    const int wm = wid >> 2;
    const int wn = wid & 3;

    const __half* srcs[2] = { A + (size_t)m0 * K, B + (size_t)n0 * K };

    const int lr = tid >> 1;
    const int lc0 = (tid & 1) * 4;
    const int lsw = lr & 7;

    auto issue = [&](int s) {
        uint32_t sb = tile + (uint32_t)(s % NSTAGE) * STAGE_F16;
        int k0 = s * 64;
#pragma unroll
        for (int p = 0; p < 2; p++) {
            const __half* g = srcs[p] + (size_t)lr * K + k0 + lc0 * 8;
            uint32_t base = sb + p * PART_B + lr * 128;
#pragma unroll
            for (int c = 0; c < 4; c++)
                cp16(base + (((lc0 + c) ^ lsw) << 4), g + c * 8);
        }
        CP_COMMIT();
    };

    const int arow = wm * 64 + (lane & 15);
    const int ahalf = lane >> 4;
    const int asw = arow & 7;
    const int brow = wn * 32 + ((lane >> 4) << 3) + (lane & 7);
    const int bhalf = (lane >> 3) & 1;
    const int bsw = brow & 7;

    float acc[4][4][4];
#pragma unroll
    for (int i = 0; i < 4; i++)
#pragma unroll
        for (int j = 0; j < 4; j++)
#pragma unroll
            for (int c = 0; c < 4; c++) acc[i][j][c] = 0.f;

    issue(0); issue(1);

    const int NIT = K / 64;
    for (int it = 0; it < NIT; ++it) {
        if (it + 1 < NIT) asm volatile("cp.async.wait_group 1;" ::: "memory");
        else              asm volatile("cp.async.wait_group 0;" ::: "memory");
        __syncthreads();
        if (it + 2 < NIT) issue(it + 2);

        uint32_t sb = tile + (uint32_t)(it % NSTAGE) * STAGE_F16;
        uint32_t aA = sb          + arow * 128;
        uint32_t aB = sb + PART_B + brow * 128;

#pragma unroll
        for (int ks = 0; ks < 4; ks++) {
            const int ac = (2 * ks + ahalf) ^ asw;
            const int bc = (2 * ks + bhalf) ^ bsw;
            uint32_t a[4][4], b[4][2];
#pragma unroll
            for (int i = 0; i < 4; i++)
                ldsm4(a[i], aA + i * (16 * 128) + (ac << 4));
#pragma unroll
            for (int q = 0; q < 2; q++) {
                uint32_t rb[4];
                ldsm4(rb, aB + q * (16 * 128) + (bc << 4));
                b[q*2+0][0] = rb[0]; b[q*2+0][1] = rb[1];
                b[q*2+1][0] = rb[2]; b[q*2+1][1] = rb[3];
            }
#pragma unroll
            for (int i = 0; i < 4; i++)
#pragma unroll
                for (int j = 0; j < 4; j++)
                    MMA_F16(acc[i][j], a[i], b[j]);
        }
    }

    const int g = lane >> 2, tq = lane & 3;
#pragma unroll
    for (int i = 0; i < 4; i++) {
        const int m = m0 + wm * 64 + i * 16 + g;
#pragma unroll
        for (int j = 0; j < 4; j++) {
            const int n = n0 + wn * 32 + j * 8 + tq * 2;
            float b0 = bias[n], b1 = bias[n + 1];
            float2 v0 = { acc[i][j][0] + b0, acc[i][j][1] + b1 };
            float2 v1 = { acc[i][j][2] + b0, acc[i][j][3] + b1 };
            *reinterpret_cast<float2*>(C + (size_t)m * N + n)       = v0;
            *reinterpret_cast<float2*>(C + (size_t)(m + 8) * N + n) = v1;
        }
    }
}

// ----- pass B: warp-parallel affine scan across 128 chunk summaries ------------
__global__ __launch_bounds__(256) void scan_carry(
    const float* __restrict__ cA, const float* __restrict__ cB,
    float* __restrict__ pref)
{
    const int gw = (blockIdx.x * 256 + threadIdx.x) >> 5;   // warp id 0..4095
    const int lane = threadIdx.x & 31;
    const int h = gw % CH;
    const int b = gw / CH;
    const size_t base = (size_t)b * NCHUNK * CH + h;

    float a[4], v[4];
#pragma unroll
    for (int i = 0; i < 4; i++) {
        size_t o = base + (size_t)(lane * 4 + i) * CH;
        a[i] = cA[o];
        v[i] = cB[o];
    }
    float A = a[0], B = v[0];
#pragma unroll
    for (int i = 1; i < 4; i++) {
        B = fmaf(a[i], B, v[i]);
        A = a[i] * A;
    }
#pragma unroll
    for (int off = 1; off < 32; off <<= 1) {
        float Ap = __shfl_up_sync(0xffffffffu, A, off);
        float Bp = __shfl_up_sync(0xffffffffu, B, off);
        if (lane >= off) {
            B = fmaf(A, Bp, B);
            A = A * Ap;
        }
    }
    float Be = __shfl_up_sync(0xffffffffu, B, 1);
    float run = (lane == 0) ? 0.f : Be;
#pragma unroll
    for (int i = 0; i < 4; i++) {
        size_t o = base + (size_t)(lane * 4 + i) * CH;
        pref[o] = run;
        run = fmaf(a[i], run, v[i]);
    }
}

// ------- pass C: one WARP per row; shfl-only LN reduction (no smem/barriers) ---
__global__ __launch_bounds__(256) void fix_ln(
    const __half2* __restrict__ PH,
    const float* __restrict__ pref,
    const float* __restrict__ lng, const float* __restrict__ lnb,
    __half* __restrict__ hnh)
{
    const int row = blockIdx.x * 8 + (threadIdx.x >> 5);
    const int lane = threadIdx.x & 31;
    const int b = row / CT;
    const int t = row % CT;
    const int c = t / CHUNK;
    const size_t base = (size_t)row * CH;
    const float* prow = pref + ((size_t)b * NCHUNK + c) * CH;

    float v[8][4];
    float s = 0.f, ss = 0.f;
#pragma unroll
    for (int i = 0; i < 8; i++) {
        const int h = lane * 4 + i * 128;
        uint4 q = *reinterpret_cast<const uint4*>(PH + base + h);
        float4 pr = *reinterpret_cast<const float4*>(prow + h);
        float2 q0 = __half22float2(*reinterpret_cast<__half2*>(&q.x));
        float2 q1 = __half22float2(*reinterpret_cast<__half2*>(&q.y));
        float2 q2 = __half22float2(*reinterpret_cast<__half2*>(&q.z));
        float2 q3 = __half22float2(*reinterpret_cast<__half2*>(&q.w));
        v[i][0] = fmaf(q0.x, pr.x, q0.y);
        v[i][1] = fmaf(q1.x, pr.y, q1.y);
        v[i][2] = fmaf(q2.x, pr.z, q2.y);
        v[i][3] = fmaf(q3.x, pr.w, q3.y);
#pragma unroll
        for (int k = 0; k < 4; k++) {
            s += v[i][k];
            ss = fmaf(v[i][k], v[i][k], ss);
        }
    }
#pragma unroll
    for (int off = 16; off > 0; off >>= 1) {
        s  += __shfl_xor_sync(0xffffffffu, s,  off);
        ss += __shfl_xor_sync(0xffffffffu, ss, off);
    }
    const float mu  = s * (1.f / CH);
    const float var = ss * (1.f / CH) - mu * mu;
    const float inv = rsqrtf(var + LN_EPS);

#pragma unroll
    for (int i = 0; i < 8; i++) {
        const int h = lane * 4 + i * 128;
        float4 g4 = *reinterpret_cast<const float4*>(lng + h);
        float4 b4 = *reinterpret_cast<const float4*>(lnb + h);
        float o0 = (v[i][0] - mu) * inv * g4.x + b4.x;
        float o1 = (v[i][1] - mu) * inv * g4.y + b4.y;
        float o2 = (v[i][2] - mu) * inv * g4.z + b4.z;
        float o3 = (v[i][3] - mu) * inv * g4.w + b4.w;
        uint2 ou;
        *reinterpret_cast<__half2*>(&ou.x) = __floats2half2_rn(o0, o1);
        *reinterpret_cast<__half2*>(&ou.y) = __floats2half2_rn(o2, o3);
        *reinterpret_cast<uint2*>(hnh + base + h) = ou;
    }
}

// --------------------------------- launcher ----------------------------------
extern "C" void kernel_launch(void* const* d_in, const int* in_sizes, int n_in,
                              void* d_out, int out_size)
{
    const float* x      = (const float*)d_in[0];
    const float* W_ih   = (const float*)d_in[1];
    const float* b_ih   = (const float*)d_in[2];
    const float* log_a  = (const float*)d_in[3];
    const float* W_gate = (const float*)d_in[4];
    const float* b_gate = (const float*)d_in[5];
    const float* W_out  = (const float*)d_in[6];
    const float* b_out  = (const float*)d_in[7];
    const float* ln_g   = (const float*)d_in[8];
    const float* ln_b   = (const float*)d_in[9];
    float* out = (float*)d_out;

    __half *xh, *w1h, *w2h, *w3h, *hnh;
    __half2 *PH;
    float *cA, *cB, *pref;
    cudaGetSymbolAddress((void**)&xh,   g_xh);
    cudaGetSymbolAddress((void**)&w1h,  g_w1h);
    cudaGetSymbolAddress((void**)&w2h,  g_w2h);
    cudaGetSymbolAddress((void**)&w3h,  g_w3h);
    cudaGetSymbolAddress((void**)&hnh,  g_hnh);
    cudaGetSymbolAddress((void**)&PH,   g_PH);
    cudaGetSymbolAddress((void**)&cA,   g_cA);
    cudaGetSymbolAddress((void**)&cB,   g_cB);
    cudaGetSymbolAddress((void**)&pref, g_pref);

    cudaFuncSetAttribute(gemm_scan,
                         cudaFuncAttributeMaxDynamicSharedMemorySize, DYN3);
    cudaFuncSetAttribute(gemm_f16,
                         cudaFuncAttributeMaxDynamicSharedMemorySize, DYN_F16);

    // fused conversions
    const int NBX = (int)((size_t)CM * CD / 4 / 256);
    const int NBW = (int)((size_t)CH * CD / 4 / 256);
    tofp16_all<<<NBX + 3 * NBW, 256>>>(
        x, xh, NBX, W_ih, w1h, NBW, W_gate, w2h, W_out, w3h);

    // fused dual GEMM + elementwise + local scan (128x64 tiles, 2 CTA/SM)
    gemm_scan<<<dim3(CH / 64, CM / 128), 256, DYN3>>>(
        xh, w1h, w2h, b_ih, b_gate, log_a, PH, cA, cB);

    // warp-parallel chunk-carry scan
    scan_carry<<<(CB * CH * 32) / 256, 256>>>(cA, cB, pref);
    // warp-per-row LayerNorm fixup (no barriers)
    fix_ln<<<CM / 8, 256>>>(PH, pref, ln_g, ln_b, hnh);

    // output GEMM
    gemm_f16<<<dim3(CO / 128, CM / 128), 256, DYN_F16>>>(
        hnh, w3h, b_out, out, CM, CO, CH);
}